// round 14
// baseline (speedup 1.0000x reference)
#include <cuda_runtime.h>
#include <cuda_bf16.h>
#include <cstdint>
#include <cmath>

// Problem constants
#define BB 8
#define TT 16
#define DD 4096
#define MM 4096
#define HQ 32
#define HK 8
#define DKH 128
#define NROWS 128      // B*T
#define MULT 0.08838834764831845f

// Output layout (fp32 elements): out | kc | vc | new_step
#define OFF_KC   (524288)
#define OFF_VC   (OFF_KC + 33554432)
#define OFF_STEP (OFF_VC + 33554432)

// ---------------- scratch (device globals; no allocation allowed) -------------
__device__ float g_pqkv[NROWS * 6144];      // fused qkv proj (q|k|v cols)
__device__ float g_knew[NROWS * 1024];      // rope'd k (new rows)
__device__ __align__(16) __nv_bfloat16 g_qh[8 * 8 * 64 * 128];  // rope'd q hi
__device__ __align__(16) __nv_bfloat16 g_ql[8 * 8 * 64 * 128];  // rope'd q lo
__device__ __align__(16) __nv_bfloat16 g_ah[3 * NROWS * 4096];  // pre-split A hi (q|k|v)
__device__ __align__(16) __nv_bfloat16 g_al[3 * NROWS * 4096];  // pre-split A lo
__device__ float g_part[8388608];           // split-K partials
__device__ float g_pacc[2048L * 64 * 128];  // partial PV accumulators
__device__ float g_pl[2048 * 64];           // partial softmax denominators
__device__ int   g_wflag;                   // 0=int8 packed, 1=int32, 2=float32

// ---------------- weight dtype detection -------------------------------------
__global__ void detect_wdtype(const void* __restrict__ w) {
    int tid = threadIdx.x;
    const int* wi = (const int*)w;
    int v = wi[tid];
    bool small = (v >= -127 && v <= 127);
    int all_small = __syncthreads_and((int)small);
    if (all_small) { if (tid == 0) g_wflag = 1; return; }
    float fv = __int_as_float(v);
    bool isf = isfinite(fv) && fabsf(fv) <= 127.0f && fv == rintf(fv);
    int all_f = __syncthreads_and((int)isf);
    if (tid == 0) g_wflag = all_f ? 2 : 0;
}

// ---------------- SM-path cache copy (side stream) ---------------------------
__global__ void copy_cache(const uint4* __restrict__ src_k, uint4* __restrict__ dst_k,
                           const uint4* __restrict__ src_v, uint4* __restrict__ dst_v)
{
    const long n4 = 8388608;   // 33554432 floats / 4
    long stride = (long)gridDim.x * blockDim.x;
    for (long i = (long)blockIdx.x * blockDim.x + threadIdx.x; i < n4; i += stride) {
        dst_k[i] = src_k[i];
        dst_v[i] = src_v[i];
    }
}

// ---------------- tensor-core / async helpers ---------------------------------
__device__ __forceinline__ uint32_t cvta_s(const void* p) {
    return (uint32_t)__cvta_generic_to_shared(p);
}
__device__ __forceinline__ void ldsm_x4(uint32_t* r, uint32_t a) {
    asm volatile("ldmatrix.sync.aligned.m8n8.x4.shared.b16 {%0,%1,%2,%3}, [%4];"
        : "=r"(r[0]), "=r"(r[1]), "=r"(r[2]), "=r"(r[3]) : "r"(a));
}
__device__ __forceinline__ void ldsm_x2t(uint32_t* r, uint32_t a) {
    asm volatile("ldmatrix.sync.aligned.m8n8.x2.trans.shared.b16 {%0,%1}, [%2];"
        : "=r"(r[0]), "=r"(r[1]) : "r"(a));
}
__device__ __forceinline__ void ldsm_x2(uint32_t* r, uint32_t a) {
    asm volatile("ldmatrix.sync.aligned.m8n8.x2.shared.b16 {%0,%1}, [%2];"
        : "=r"(r[0]), "=r"(r[1]) : "r"(a));
}
__device__ __forceinline__ void mma_bf16(float* c, const uint32_t* a, const uint32_t* b) {
    asm volatile("mma.sync.aligned.m16n8k16.row.col.f32.bf16.bf16.f32 "
        "{%0,%1,%2,%3}, {%4,%5,%6,%7}, {%8,%9}, {%0,%1,%2,%3};"
        : "+f"(c[0]), "+f"(c[1]), "+f"(c[2]), "+f"(c[3])
        : "r"(a[0]), "r"(a[1]), "r"(a[2]), "r"(a[3]), "r"(b[0]), "r"(b[1]));
}
__device__ __forceinline__ void cp16(uint32_t dst, const void* src) {
    asm volatile("cp.async.cg.shared.global [%0], [%1], 16;" :: "r"(dst), "l"(src));
}
__device__ __forceinline__ void cp_commit() {
    asm volatile("cp.async.commit_group;");
}
__device__ __forceinline__ void cp_wait0() {
    asm volatile("cp.async.wait_group 0;");
}
__device__ __forceinline__ __nv_bfloat162 split_hi2(float a, float b, __nv_bfloat162* lo) {
    __nv_bfloat16 h0 = __float2bfloat16(a);
    __nv_bfloat16 h1 = __float2bfloat16(b);
    *lo = __halves2bfloat162(__float2bfloat16(a - __bfloat162float(h0)),
                             __float2bfloat16(b - __bfloat162float(h1)));
    return __halves2bfloat162(h0, h1);
}

// ---------------- A pre-split (q|k|v fused) -----------------------------------
__global__ void presplit_all(const float* __restrict__ q,
                             const float* __restrict__ k,
                             const float* __restrict__ v) {
    int idx = blockIdx.x * blockDim.x + threadIdx.x;   // 3*524288
    int sel = idx >> 19;
    int off = idx & 524287;
    const float* src = (sel == 0) ? q : (sel == 1) ? k : v;
    float a = src[off];
    __nv_bfloat16 h = __float2bfloat16(a);
    g_ah[idx] = h;
    g_al[idx] = __float2bfloat16(a - __bfloat162float(h));
}

// ---------------- pipelined split-bf16 tensor-core GEMM -----------------------
// mode 0: fused QKV (Nout=6144), mode 1: single (Nout=4096)
#define LDA 40
#define LDW 72
#define GEMM_SMEM ((4 * 128 * LDA + 4 * 32 * LDW) * 2)
__global__ __launch_bounds__(256, 3) void gemm_tc(
    const __nv_bfloat16* __restrict__ AhBase, const __nv_bfloat16* __restrict__ AlBase,
    const void* __restrict__ W0, const float* __restrict__ S0,
    const void* __restrict__ W1, const float* __restrict__ S1,
    const void* __restrict__ W2, const float* __restrict__ S2,
    float* __restrict__ P, int mode, int kchunk)
{
    extern __shared__ __nv_bfloat16 smg[];
    __nv_bfloat16* sA_h = smg;                     // [2][128*LDA]
    __nv_bfloat16* sA_l = smg + 2 * 128 * LDA;
    __nv_bfloat16* sW_h = smg + 4 * 128 * LDA;     // [2][32*LDW]
    __nv_bfloat16* sW_l = smg + 4 * 128 * LDA + 2 * 32 * LDW;

    const int K = 4096;
    int bn = blockIdx.x * 64;
    int ks = blockIdx.y;
    int kbeg = ks * kchunk;
    int tid = threadIdx.x;
    int wid = tid >> 5, lane = tid & 31;
    int wf = g_wflag;

    const void* W; const float* S; int Nw, bnl, Nout, asel;
    if (mode == 0) {
        Nout = 6144;
        if (bn < 4096)      { W = W0; S = S0; Nw = 4096; bnl = bn;        asel = 0; }
        else if (bn < 5120) { W = W1; S = S1; Nw = 1024; bnl = bn - 4096; asel = 1; }
        else                { W = W2; S = S2; Nw = 1024; bnl = bn - 5120; asel = 2; }
    } else { W = W0; S = S0; Nw = 4096; bnl = bn; Nout = 4096; asel = 0; }
    const __nv_bfloat16* Ah = AhBase + (long)asel * 524288;
    const __nv_bfloat16* Al = AlBase + (long)asel * 524288;

    int warp_m = (wid >> 1) * 32;
    int warp_n = (wid & 1) * 32;

    float acc[2][4][4];
#pragma unroll
    for (int mi = 0; mi < 2; mi++)
#pragma unroll
        for (int ni = 0; ni < 4; ni++)
#pragma unroll
            for (int f = 0; f < 4; f++) acc[mi][ni][f] = 0.f;

    int arow = tid >> 1, aseg = (tid & 1) * 16;
    int wrow = tid >> 3, wnoff = (tid & 7) * 8;

    uint4 rwa = {0,0,0,0}, rwb = {0,0,0,0};
    float4 rs0, rs1;

    auto cpA = [&](int kt, int buf) {
        long go = (long)arow * K + kt + aseg;
        uint32_t dh = cvta_s(sA_h + buf * 128 * LDA + arow * LDA + aseg);
        uint32_t dl = cvta_s(sA_l + buf * 128 * LDA + arow * LDA + aseg);
        cp16(dh, Ah + go);      cp16(dh + 16, Ah + go + 8);
        cp16(dl, Al + go);      cp16(dl + 16, Al + go + 8);
    };
    auto loadW = [&](int kt) {
        long wo = (long)(kt + wrow) * Nw + bnl + wnoff;
        if (wf == 1) {
            rwa = *(const uint4*)((const int*)W + wo);
            rwb = *(const uint4*)((const int*)W + wo + 4);
        } else if (wf == 0) {
            uint2 r8 = *(const uint2*)((const int8_t*)W + wo);
            rwa.x = r8.x; rwa.y = r8.y;
        } else {
            rwa = *(const uint4*)((const float*)W + wo);
            rwb = *(const uint4*)((const float*)W + wo + 4);
        }
        rs0 = *(const float4*)(S + wo);
        rs1 = *(const float4*)(S + wo + 4);
    };
    auto storeW = [&](int buf) {
        float wd[8];
        if (wf == 1) {
            wd[0] = (float)(int)rwa.x; wd[1] = (float)(int)rwa.y;
            wd[2] = (float)(int)rwa.z; wd[3] = (float)(int)rwa.w;
            wd[4] = (float)(int)rwb.x; wd[5] = (float)(int)rwb.y;
            wd[6] = (float)(int)rwb.z; wd[7] = (float)(int)rwb.w;
        } else if (wf == 0) {
#pragma unroll
            for (int i = 0; i < 4; i++) wd[i]     = (float)(int)(char)(rwa.x >> (8 * i));
#pragma unroll
            for (int i = 0; i < 4; i++) wd[4 + i] = (float)(int)(char)(rwa.y >> (8 * i));
        } else {
            wd[0] = __uint_as_float(rwa.x); wd[1] = __uint_as_float(rwa.y);
            wd[2] = __uint_as_float(rwa.z); wd[3] = __uint_as_float(rwa.w);
            wd[4] = __uint_as_float(rwb.x); wd[5] = __uint_as_float(rwb.y);
            wd[6] = __uint_as_float(rwb.z); wd[7] = __uint_as_float(rwb.w);
        }
        float sc[8] = {rs0.x, rs0.y, rs0.z, rs0.w, rs1.x, rs1.y, rs1.z, rs1.w};
        __nv_bfloat16* bh = sW_h + buf * 32 * LDW + wrow * LDW + wnoff;
        __nv_bfloat16* bl = sW_l + buf * 32 * LDW + wrow * LDW + wnoff;
#pragma unroll
        for (int j = 0; j < 8; j += 2) {
            __nv_bfloat162 lo;
            __nv_bfloat162 hi = split_hi2(wd[j] * sc[j], wd[j + 1] * sc[j + 1], &lo);
            *(__nv_bfloat162*)&bh[j] = hi;
            *(__nv_bfloat162*)&bl[j] = lo;
        }
    };

    int nb = kchunk / 32;
    cpA(kbeg, 0); cp_commit();
    loadW(kbeg);

    for (int it = 0; it < nb; it++) {
        int cur = it & 1;
        storeW(cur);
        cp_wait0();
        __syncthreads();
        if (it + 1 < nb) {
            cpA(kbeg + (it + 1) * 32, cur ^ 1); cp_commit();
            loadW(kbeg + (it + 1) * 32);
        }
        const __nv_bfloat16* aH = sA_h + cur * 128 * LDA;
        const __nv_bfloat16* aL = sA_l + cur * 128 * LDA;
        const __nv_bfloat16* wH = sW_h + cur * 32 * LDW;
        const __nv_bfloat16* wL = sW_l + cur * 32 * LDW;
#pragma unroll
        for (int kk = 0; kk < 32; kk += 16) {
            uint32_t ah[2][4], al[2][4];
#pragma unroll
            for (int mi = 0; mi < 2; mi++) {
                int r = warp_m + mi * 16 + (lane & 15);
                int c = kk + (lane >> 4) * 8;
                ldsm_x4(ah[mi], cvta_s(&aH[r * LDA + c]));
                ldsm_x4(al[mi], cvta_s(&aL[r * LDA + c]));
            }
            uint32_t bh[4][2], bl[4][2];
#pragma unroll
            for (int ni = 0; ni < 4; ni++) {
                int r = kk + (lane & 15);
                int c = warp_n + ni * 8;
                ldsm_x2t(bh[ni], cvta_s(&wH[r * LDW + c]));
                ldsm_x2t(bl[ni], cvta_s(&wL[r * LDW + c]));
            }
#pragma unroll
            for (int mi = 0; mi < 2; mi++)
#pragma unroll
                for (int ni = 0; ni < 4; ni++) {
                    mma_bf16(acc[mi][ni], ah[mi], bh[ni]);
                    mma_bf16(acc[mi][ni], ah[mi], bl[ni]);
                    mma_bf16(acc[mi][ni], al[mi], bh[ni]);
                }
        }
    }

    float* base = P + (long)ks * NROWS * Nout;
    int r0 = lane >> 2, c0 = (lane & 3) * 2;
#pragma unroll
    for (int mi = 0; mi < 2; mi++)
#pragma unroll
        for (int ni = 0; ni < 4; ni++) {
            float* cp = base + (long)(warp_m + mi * 16 + r0) * Nout + bn + warp_n + ni * 8 + c0;
            cp[0] = acc[mi][ni][0];
            cp[1] = acc[mi][ni][1];
            float* cp2 = cp + 8 * (long)Nout;
            cp2[0] = acc[mi][ni][2];
            cp2[1] = acc[mi][ni][3];
        }
}

// ---------------- split-K reduce ----------------------------------------------
__global__ void reduce_splitk(const float* __restrict__ P, float* __restrict__ C,
                              int size4, int nsplit)
{
    int idx = blockIdx.x * blockDim.x + threadIdx.x;
    if (idx >= size4) return;
    const float4* P4 = (const float4*)P;
    float4 s = P4[idx];
    for (int k = 1; k < nsplit; k++) {
        float4 v = P4[(long)k * size4 + idx];
        s.x += v.x; s.y += v.y; s.z += v.z; s.w += v.w;
    }
    ((float4*)C)[idx] = s;
}

// ---------------- fused RoPE (q -> g_qh/g_ql split, k -> g_knew) + step ------
__global__ void rope_fused(const int* __restrict__ step, float* __restrict__ ostep) {
    int idx = blockIdx.x * blockDim.x + threadIdx.x;  // 262144 + 65536
    if (blockIdx.x == 0 && threadIdx.x < BB)
        ostep[threadIdx.x] = (float)(step[threadIdx.x] + TT);
    if (idx < 262144) {
        int row = idx >> 11;
        int rem = idx & 2047;
        int h = rem >> 6, j = rem & 63;
        int b = row >> 4, t = row & 15;
        float x1 = g_pqkv[(long)row * 6144 + h * 128 + j];
        float x2 = g_pqkv[(long)row * 6144 + h * 128 + j + 64];
        float pos = (float)(t + step[b]);
        float invf = (float)exp(-(double)j * 0.14391156831212787);
        float ph = pos * invf;
        float c = cosf(ph), s = sinf(ph);
        float y1 = x1 * c - x2 * s;
        float y2 = x2 * c + x1 * s;
        int kvh = h >> 2, hg = h & 3;
        long orow = ((long)(b * 8 + kvh)) * 64 + hg * 16 + t;
        __nv_bfloat16 h1 = __float2bfloat16(y1);
        __nv_bfloat16 h2 = __float2bfloat16(y2);
        g_qh[orow * 128 + j]      = h1;
        g_ql[orow * 128 + j]      = __float2bfloat16(y1 - __bfloat162float(h1));
        g_qh[orow * 128 + j + 64] = h2;
        g_ql[orow * 128 + j + 64] = __float2bfloat16(y2 - __bfloat162float(h2));
    } else {
        int i2 = idx - 262144;     // 65536 k elems
        int row = i2 >> 9;
        int rem = i2 & 511;
        int h = rem >> 6, j = rem & 63;
        int b = row >> 4, t = row & 15;
        float x1 = g_pqkv[(long)row * 6144 + 4096 + h * 128 + j];
        float x2 = g_pqkv[(long)row * 6144 + 4096 + h * 128 + j + 64];
        int pos = t + step[b];
        float invf = (float)exp(-(double)j * 0.14391156831212787);
        float ph = (float)pos * invf;
        float c = cosf(ph), s = sinf(ph);
        float* dst = g_knew + (long)row * 1024 + h * 128;
        dst[j]      = x1 * c - x2 * s;
        dst[j + 64] = x2 * c + x1 * s;
    }
}

// ---------------- final scatter of new rows into kc/vc ------------------------
__global__ void scatter_new(const int* __restrict__ step,
                            float* __restrict__ kc, float* __restrict__ vc) {
    int idx = blockIdx.x * blockDim.x + threadIdx.x;   // 128*1024
    int row = idx >> 10;
    int rem = idx & 1023;
    int b = row >> 4, t = row & 15;
    int h = rem >> 7, d = rem & 127;
    long gi = (((long)b * MM + (step[b] + t)) * HK + h) * DKH + d;
    kc[gi] = g_knew[idx];
    vc[gi] = g_pqkv[(long)row * 6144 + 5120 + rem];
}

// ---------------- Tensor-core attention partial (per b, kvh, 128-key chunk) --
#define LDQ 136
#define LDK 136
#define LDV 136
#define LDP 136
#define ATTN_SMEM (((2*64*LDQ + 2*128*LDK + 2*128*LDV + 2*64*LDP) * 2) + 256)
__global__ __launch_bounds__(256) void attn_tc(
    const float* __restrict__ mem_k, const float* __restrict__ mem_v,
    const int* __restrict__ step)
{
    extern __shared__ char smraw[];
    __nv_bfloat16* sQh = (__nv_bfloat16*)smraw;
    __nv_bfloat16* sQl = sQh + 64 * LDQ;
    __nv_bfloat16* sKh = sQl + 64 * LDQ;
    __nv_bfloat16* sKl = sKh + 128 * LDK;
    __nv_bfloat16* sVh = sKl + 128 * LDK;
    __nv_bfloat16* sVl = sVh + 128 * LDV;
    __nv_bfloat16* sPh = sVl + 128 * LDV;
    __nv_bfloat16* sPl = sPh + 64 * LDP;
    float* sRow = (float*)(sPl + 64 * LDP);

    int chunk = blockIdx.x, kvh = blockIdx.y, b = blockIdx.z;
    int tid = threadIdx.x;
    int wid = tid >> 5, lane = tid & 31;
    int j0 = chunk * 128;
    int stepb = step[b];
    int nstep = stepb + TT;
    if (j0 >= nstep) return;

    if (tid < 64) sRow[tid] = 0.f;

    // ---- stage Q ----
    {
        const uint4* qh = (const uint4*)(g_qh + ((long)(b * 8 + kvh)) * 64 * 128);
        const uint4* ql = (const uint4*)(g_ql + ((long)(b * 8 + kvh)) * 64 * 128);
        for (int i = tid; i < 1024; i += 256) {
            int qi = i >> 4, seg = (i & 15) * 8;
            *(uint4*)&sQh[qi * LDQ + seg] = qh[i];
            *(uint4*)&sQl[qi * LDQ + seg] = ql[i];
        }
    }
    // ---- stage K rows [jj][d] + split ----
    {
        int jj = tid >> 1, dh = (tid & 1) * 64;
        int pos = j0 + jj;
        int rel = pos - stepb;
        const float* kp = (rel >= 0 && rel < TT)
            ? g_knew + ((long)(b * 16 + rel)) * 1024 + kvh * 128 + dh
            : mem_k + (((long)b * MM + pos) * HK + kvh) * DKH + dh;
#pragma unroll
        for (int i = 0; i < 16; i++) {
            float4 v = *(const float4*)(kp + i * 4);
            float x[4] = {v.x, v.y, v.z, v.w};
#pragma unroll
            for (int u = 0; u < 4; u += 2) {
                __nv_bfloat162 lo;
                __nv_bfloat162 hi = split_hi2(x[u], x[u + 1], &lo);
                int d = dh + i * 4 + u;
                *(__nv_bfloat162*)&sKh[jj * LDK + d] = hi;
                *(__nv_bfloat162*)&sKl[jj * LDK + d] = lo;
            }
        }
    }
    // ---- stage V rows [jj][d] + split ----
    {
        int jj = tid >> 1, dh = (tid & 1) * 64;
        int pos = j0 + jj;
        int rel = pos - stepb;
        const float* vp = (rel >= 0 && rel < TT)
            ? g_pqkv + ((long)(b * 16 + rel)) * 6144 + 5120 + kvh * 128 + dh
            : mem_v + (((long)b * MM + pos) * HK + kvh) * DKH + dh;
#pragma unroll
        for (int i = 0; i < 16; i++) {
            float4 v = *(const float4*)(vp + i * 4);
            float x[4] = {v.x, v.y, v.z, v.w};
#pragma unroll
            for (int u = 0; u < 4; u += 2) {
                __nv_bfloat162 lo;
                __nv_bfloat162 hi = split_hi2(x[u], x[u + 1], &lo);
                int d = dh + i * 4 + u;
                *(__nv_bfloat162*)&sVh[jj * LDV + d] = hi;
                *(__nv_bfloat162*)&sVl[jj * LDV + d] = lo;
            }
        }
    }
    __syncthreads();

    int warp_m = (wid >> 2) * 32;
    int warp_n = (wid & 3) * 32;

    // ---- QK^T (B from K rows [n][k] via non-trans ldmatrix) ----
    float acc[2][4][4];
#pragma unroll
    for (int mi = 0; mi < 2; mi++)
#pragma unroll
        for (int ni = 0; ni < 4; ni++)
#pragma unroll
            for (int f = 0; f < 4; f++) acc[mi][ni][f] = 0.f;

#pragma unroll
    for (int kk = 0; kk < 128; kk += 16) {
        uint32_t ah[2][4], al[2][4];
#pragma unroll
        for (int mi = 0; mi < 2; mi++) {
            int r = warp_m + mi * 16 + (lane & 15);
            int c = kk + (lane >> 4) * 8;
            ldsm_x4(ah[mi], cvta_s(&sQh[r * LDQ + c]));
            ldsm_x4(al[mi], cvta_s(&sQl[r * LDQ + c]));
        }
        uint32_t bh[4][2], bl[4][2];
#pragma unroll
        for (int ni = 0; ni < 4; ni++) {
            int nrow = warp_n + ni * 8 + (lane & 7);
            int kcol = kk + ((lane >> 3) & 1) * 8;
            ldsm_x2(bh[ni], cvta_s(&sKh[nrow * LDK + kcol]));
            ldsm_x2(bl[ni], cvta_s(&sKl[nrow * LDK + kcol]));
        }
#pragma unroll
        for (int mi = 0; mi < 2; mi++)
#pragma unroll
            for (int ni = 0; ni < 4; ni++) {
                mma_bf16(acc[mi][ni], ah[mi], bh[ni]);
                mma_bf16(acc[mi][ni], ah[mi], bl[ni]);
                mma_bf16(acc[mi][ni], al[mi], bh[ni]);
            }
    }

    // ---- capped softmax numerator ----
#pragma unroll
    for (int mi = 0; mi < 2; mi++) {
        int r_lo = warp_m + mi * 16 + (lane >> 2);
        int r_hi = r_lo + 8;
        float s0 = 0.f, s1 = 0.f;
#pragma unroll
        for (int ni = 0; ni < 4; ni++) {
            int c0 = warp_n + ni * 8 + (lane & 3) * 2;
            float p[4];
#pragma unroll
            for (int f = 0; f < 4; f++) {
                int jg = j0 + c0 + (f & 1);
                float u = acc[mi][ni][f] * (MULT / 30.f);
                float t2 = __expf(-2.f * fabsf(u));
                float th = __fdividef(1.f - t2, 1.f + t2);
                th = copysignf(th, u);
                p[f] = (jg < nstep) ? __expf(30.f * th) : 0.f;
            }
            s0 += p[0] + p[1];
            s1 += p[2] + p[3];
            __nv_bfloat162 lo;
            __nv_bfloat162 hi = split_hi2(p[0], p[1], &lo);
            *(__nv_bfloat162*)&sPh[r_lo * LDP + c0] = hi;
            *(__nv_bfloat162*)&sPl[r_lo * LDP + c0] = lo;
            hi = split_hi2(p[2], p[3], &lo);
            *(__nv_bfloat162*)&sPh[r_hi * LDP + c0] = hi;
            *(__nv_bfloat162*)&sPl[r_hi * LDP + c0] = lo;
        }
        s0 += __shfl_xor_sync(0xffffffff, s0, 1);
        s0 += __shfl_xor_sync(0xffffffff, s0, 2);
        s1 += __shfl_xor_sync(0xffffffff, s1, 1);
        s1 += __shfl_xor_sync(0xffffffff, s1, 2);
        if ((lane & 3) == 0) {
            atomicAdd(&sRow[r_lo], s0);
            atomicAdd(&sRow[r_hi], s1);
        }
    }
    __syncthreads();

    int pbase = (b * 8 + kvh) * 32 + chunk;
    if (tid < 64) g_pl[pbase * 64 + tid] = sRow[tid];

    // ---- PV ----
    float oacc[2][4][4];
#pragma unroll
    for (int mi = 0; mi < 2; mi++)
#pragma unroll
        for (int ni = 0; ni < 4; ni++)
#pragma unroll
            for (int f = 0; f < 4; f++) oacc[mi][ni][f] = 0.f;

#pragma unroll
    for (int kk = 0; kk < 128; kk += 16) {
        uint32_t ph[2][4], pl[2][4];
#pragma unroll
        for (int mi = 0; mi < 2; mi++) {
            int r = warp_m + mi * 16 + (lane & 15);
            int c = kk + (lane >> 4) * 8;
            ldsm_x4(ph[mi], cvta_s(&sPh[r * LDP + c]));
            ldsm_x4(pl[mi], cvta_s(&sPl[r * LDP + c]));
        }
        uint32_t vh[4][2], vl[4][2];
#pragma unroll
        for (int ni = 0; ni < 4; ni++) {
            int r = kk + (lane & 15);
            int c = warp_n + ni * 8;
            ldsm_x2t(vh[ni], cvta_s(&sVh[r * LDV + c]));
            ldsm_x2t(vl[ni], cvta_s(&sVl[r * LDV + c]));
        }
#pragma unroll
        for (int mi = 0; mi < 2; mi++)
#pragma unroll
            for (int ni = 0; ni < 4; ni++) {
                mma_bf16(oacc[mi][ni], ph[mi], vh[ni]);
                mma_bf16(oacc[mi][ni], ph[mi], vl[ni]);
                mma_bf16(oacc[mi][ni], pl[mi], vh[ni]);
            }
    }

    float* dst = &g_pacc[(long)pbase * 8192];
#pragma unroll
    for (int mi = 0; mi < 2; mi++) {
        int r_lo = warp_m + mi * 16 + (lane >> 2);
#pragma unroll
        for (int ni = 0; ni < 4; ni++) {
            int d0 = warp_n + ni * 8 + (lane & 3) * 2;
            *(float2*)&dst[r_lo * 128 + d0] = make_float2(oacc[mi][ni][0], oacc[mi][ni][1]);
            *(float2*)&dst[(r_lo + 8) * 128 + d0] = make_float2(oacc[mi][ni][2], oacc[mi][ni][3]);
        }
    }
}

// ---------------- Combine partials -> split bf16 A for O-proj ----------------
__global__ void combine_kernel(const int* __restrict__ step) {
    int blk = blockIdx.x;
    int qi = blk & 63;
    int bk = blk >> 6;
    int kvh = bk & 7, b = bk >> 3;
    int d = threadIdx.x;           // 128
    int nstep = step[b] + TT;
    int nch = (nstep + 127) >> 7;
    if (nch > 32) nch = 32;
    float asum = 0.f, lsum = 0.f;
    int base = bk * 32;
    for (int c = 0; c < nch; c++)
        asum += g_pacc[(long)(base + c) * 8192 + qi * 128 + d];
    for (int c = 0; c < nch; c++)
        lsum += g_pl[(base + c) * 64 + qi];
    int t = qi & 15, hg = qi >> 4;
    float val = asum / lsum;
    long oidx = (((long)(b * 16 + t)) * 32 + kvh * 4 + hg) * 128 + d;
    __nv_bfloat16 h = __float2bfloat16(val);
    g_ah[oidx] = h;
    g_al[oidx] = __float2bfloat16(val - __bfloat162float(h));
}

// ---------------- launch ------------------------------------------------------
extern "C" void kernel_launch(void* const* d_in, const int* in_sizes, int n_in,
                              void* d_out, int out_size)
{
    const float*   query = (const float*)d_in[0];
    const float*   keyx  = (const float*)d_in[1];
    const float*   value = (const float*)d_in[2];
    const float*   mem_k = (const float*)d_in[4];
    const float*   mem_v = (const float*)d_in[5];
    const int*     step  = (const int*)d_in[6];
    const void*    wq = d_in[7];
    const float*   sq = (const float*)d_in[8];
    const void*    wk = d_in[9];
    const float*   sk = (const float*)d_in[10];
    const void*    wv = d_in[11];
    const float*   sv = (const float*)d_in[12];
    const void*    wo = d_in[13];
    const float*   so = (const float*)d_in[14];

    float* out = (float*)d_out;
    float* kc    = out + OFF_KC;
    float* vc    = out + OFF_VC;
    float* ostep = out + OFF_STEP;

    // Side stream (created once) for the independent full cache copy.
    static cudaStream_t s1 = nullptr;
    static cudaEvent_t ev0 = nullptr, ev1 = nullptr;
    static bool sok = false;
    if (!s1) {
        sok = (cudaStreamCreateWithFlags(&s1, cudaStreamNonBlocking) == cudaSuccess) &&
              (cudaEventCreateWithFlags(&ev0, cudaEventDisableTiming) == cudaSuccess) &&
              (cudaEventCreateWithFlags(&ev1, cudaEventDisableTiming) == cudaSuccess);
    }

    if (sok) {
        cudaEventRecord(ev0, 0);
        cudaStreamWaitEvent(s1, ev0, 0);
        copy_cache<<<512, 256, 0, s1>>>((const uint4*)mem_k, (uint4*)kc,
                                        (const uint4*)mem_v, (uint4*)vc);
        cudaEventRecord(ev1, s1);
    } else {
        copy_cache<<<512, 256>>>((const uint4*)mem_k, (uint4*)kc,
                                 (const uint4*)mem_v, (uint4*)vc);
    }

    detect_wdtype<<<1, 256>>>(wq);

    float *pqkv, *part;
    __nv_bfloat16 *ah, *al;
    cudaGetSymbolAddress((void**)&pqkv, g_pqkv);
    cudaGetSymbolAddress((void**)&part, g_part);
    cudaGetSymbolAddress((void**)&ah, g_ah);
    cudaGetSymbolAddress((void**)&al, g_al);

    cudaFuncSetAttribute(gemm_tc, cudaFuncAttributeMaxDynamicSharedMemorySize, GEMM_SMEM);
    cudaFuncSetAttribute(attn_tc, cudaFuncAttributeMaxDynamicSharedMemorySize, ATTN_SMEM);

    // Fused QKV projection: 4-way split-K (kchunk=1024) — halves partial traffic
    presplit_all<<<1536, 1024>>>(query, keyx, value);
    gemm_tc<<<dim3(96, 4), 256, GEMM_SMEM>>>(ah, al, wq, sq, wk, sk, wv, sv,
                                             part, 0, 1024);
    reduce_splitk<<<768, 256>>>(part, pqkv, 196608, 4);

    // RoPE + new_step
    rope_fused<<<1280, 256>>>(step, ostep);

    // Tensor-core attention (lean: reads mem_k/mem_v + new-row scratch)
    attn_tc<<<dim3(32, 8, 8), 256, ATTN_SMEM>>>(mem_k, mem_v, step);
    combine_kernel<<<4096, 128>>>(step);

    // Output projection: 8-way split-K (kchunk=512)
    gemm_tc<<<dim3(64, 8), 256, GEMM_SMEM>>>(ah, al, wo, so, wo, so, wo, so,
                                             part, 1, 512);
    reduce_splitk<<<512, 256>>>(part, out, 131072, 8);

    // Join copy stream, then scatter the 16 new rows into kc/vc
    if (sok) cudaStreamWaitEvent(0, ev1, 0);
    scatter_new<<<512, 256>>>(step, kc, vc);
}

// round 15
// speedup vs baseline: 1.0372x; 1.0372x over previous
#include <cuda_runtime.h>
#include <cuda_bf16.h>
#include <cstdint>
#include <cmath>

// Problem constants
#define BB 8
#define TT 16
#define DD 4096
#define MM 4096
#define HQ 32
#define HK 8
#define DKH 128
#define NROWS 128      // B*T
#define MULT 0.08838834764831845f

// Output layout (fp32 elements): out | kc | vc | new_step
#define OFF_KC   (524288)
#define OFF_VC   (OFF_KC + 33554432)
#define OFF_STEP (OFF_VC + 33554432)

// ---------------- scratch (device globals; no allocation allowed) -------------
__device__ float g_pqkv[NROWS * 6144];      // fused qkv proj (q|k|v cols)
__device__ float g_knew[NROWS * 1024];      // rope'd k (new rows)
__device__ __align__(16) __nv_bfloat16 g_qh[8 * 8 * 64 * 128];  // rope'd q hi
__device__ __align__(16) __nv_bfloat16 g_ql[8 * 8 * 64 * 128];  // rope'd q lo
__device__ __align__(16) __nv_bfloat16 g_ah[3 * NROWS * 4096];  // pre-split A hi (q|k|v)
__device__ __align__(16) __nv_bfloat16 g_al[3 * NROWS * 4096];  // pre-split A lo
__device__ float g_part[8388608];           // split-K partials
__device__ float g_pacc[4096L * 64 * 128];  // partial PV accumulators (134MB)
__device__ float g_pl[4096 * 64];           // partial softmax denominators
__device__ int   g_wflag;                   // 0=int8 packed, 1=int32, 2=float32

// ---------------- weight dtype detection -------------------------------------
__global__ void detect_wdtype(const void* __restrict__ w) {
    int tid = threadIdx.x;
    const int* wi = (const int*)w;
    int v = wi[tid];
    bool small = (v >= -127 && v <= 127);
    int all_small = __syncthreads_and((int)small);
    if (all_small) { if (tid == 0) g_wflag = 1; return; }
    float fv = __int_as_float(v);
    bool isf = isfinite(fv) && fabsf(fv) <= 127.0f && fv == rintf(fv);
    int all_f = __syncthreads_and((int)isf);
    if (tid == 0) g_wflag = all_f ? 2 : 0;
}

// ---------------- SM-path cache copy (side stream) ---------------------------
__global__ void copy_cache(const uint4* __restrict__ src_k, uint4* __restrict__ dst_k,
                           const uint4* __restrict__ src_v, uint4* __restrict__ dst_v)
{
    const long n4 = 8388608;   // 33554432 floats / 4
    long stride = (long)gridDim.x * blockDim.x;
    for (long i = (long)blockIdx.x * blockDim.x + threadIdx.x; i < n4; i += stride) {
        dst_k[i] = src_k[i];
        dst_v[i] = src_v[i];
    }
}

// ---------------- tensor-core / async helpers ---------------------------------
__device__ __forceinline__ uint32_t cvta_s(const void* p) {
    return (uint32_t)__cvta_generic_to_shared(p);
}
__device__ __forceinline__ void ldsm_x4(uint32_t* r, uint32_t a) {
    asm volatile("ldmatrix.sync.aligned.m8n8.x4.shared.b16 {%0,%1,%2,%3}, [%4];"
        : "=r"(r[0]), "=r"(r[1]), "=r"(r[2]), "=r"(r[3]) : "r"(a));
}
__device__ __forceinline__ void ldsm_x2t(uint32_t* r, uint32_t a) {
    asm volatile("ldmatrix.sync.aligned.m8n8.x2.trans.shared.b16 {%0,%1}, [%2];"
        : "=r"(r[0]), "=r"(r[1]) : "r"(a));
}
__device__ __forceinline__ void ldsm_x2(uint32_t* r, uint32_t a) {
    asm volatile("ldmatrix.sync.aligned.m8n8.x2.shared.b16 {%0,%1}, [%2];"
        : "=r"(r[0]), "=r"(r[1]) : "r"(a));
}
__device__ __forceinline__ void mma_bf16(float* c, const uint32_t* a, const uint32_t* b) {
    asm volatile("mma.sync.aligned.m16n8k16.row.col.f32.bf16.bf16.f32 "
        "{%0,%1,%2,%3}, {%4,%5,%6,%7}, {%8,%9}, {%0,%1,%2,%3};"
        : "+f"(c[0]), "+f"(c[1]), "+f"(c[2]), "+f"(c[3])
        : "r"(a[0]), "r"(a[1]), "r"(a[2]), "r"(a[3]), "r"(b[0]), "r"(b[1]));
}
__device__ __forceinline__ void cp16(uint32_t dst, const void* src) {
    asm volatile("cp.async.cg.shared.global [%0], [%1], 16;" :: "r"(dst), "l"(src));
}
__device__ __forceinline__ void cp_commit() {
    asm volatile("cp.async.commit_group;");
}
__device__ __forceinline__ void cp_wait0() {
    asm volatile("cp.async.wait_group 0;");
}
__device__ __forceinline__ __nv_bfloat162 split_hi2(float a, float b, __nv_bfloat162* lo) {
    __nv_bfloat16 h0 = __float2bfloat16(a);
    __nv_bfloat16 h1 = __float2bfloat16(b);
    *lo = __halves2bfloat162(__float2bfloat16(a - __bfloat162float(h0)),
                             __float2bfloat16(b - __bfloat162float(h1)));
    return __halves2bfloat162(h0, h1);
}

// ---------------- A pre-split (q|k|v fused) -----------------------------------
__global__ void presplit_all(const float* __restrict__ q,
                             const float* __restrict__ k,
                             const float* __restrict__ v) {
    int idx = blockIdx.x * blockDim.x + threadIdx.x;   // 3*524288
    int sel = idx >> 19;
    int off = idx & 524287;
    const float* src = (sel == 0) ? q : (sel == 1) ? k : v;
    float a = src[off];
    __nv_bfloat16 h = __float2bfloat16(a);
    g_ah[idx] = h;
    g_al[idx] = __float2bfloat16(a - __bfloat162float(h));
}

// ---------------- pipelined split-bf16 tensor-core GEMM -----------------------
// mode 0: fused QKV (Nout=6144), mode 1: single (Nout=4096)
#define LDA 40
#define LDW 72
#define GEMM_SMEM ((4 * 128 * LDA + 4 * 32 * LDW) * 2)
__global__ __launch_bounds__(256, 3) void gemm_tc(
    const __nv_bfloat16* __restrict__ AhBase, const __nv_bfloat16* __restrict__ AlBase,
    const void* __restrict__ W0, const float* __restrict__ S0,
    const void* __restrict__ W1, const float* __restrict__ S1,
    const void* __restrict__ W2, const float* __restrict__ S2,
    float* __restrict__ P, int mode, int kchunk)
{
    extern __shared__ __nv_bfloat16 smg[];
    __nv_bfloat16* sA_h = smg;                     // [2][128*LDA]
    __nv_bfloat16* sA_l = smg + 2 * 128 * LDA;
    __nv_bfloat16* sW_h = smg + 4 * 128 * LDA;     // [2][32*LDW]
    __nv_bfloat16* sW_l = smg + 4 * 128 * LDA + 2 * 32 * LDW;

    const int K = 4096;
    int bn = blockIdx.x * 64;
    int ks = blockIdx.y;
    int kbeg = ks * kchunk;
    int tid = threadIdx.x;
    int wid = tid >> 5, lane = tid & 31;
    int wf = g_wflag;

    const void* W; const float* S; int Nw, bnl, Nout, asel;
    if (mode == 0) {
        Nout = 6144;
        if (bn < 4096)      { W = W0; S = S0; Nw = 4096; bnl = bn;        asel = 0; }
        else if (bn < 5120) { W = W1; S = S1; Nw = 1024; bnl = bn - 4096; asel = 1; }
        else                { W = W2; S = S2; Nw = 1024; bnl = bn - 5120; asel = 2; }
    } else { W = W0; S = S0; Nw = 4096; bnl = bn; Nout = 4096; asel = 0; }
    const __nv_bfloat16* Ah = AhBase + (long)asel * 524288;
    const __nv_bfloat16* Al = AlBase + (long)asel * 524288;

    int warp_m = (wid >> 1) * 32;
    int warp_n = (wid & 1) * 32;

    float acc[2][4][4];
#pragma unroll
    for (int mi = 0; mi < 2; mi++)
#pragma unroll
        for (int ni = 0; ni < 4; ni++)
#pragma unroll
            for (int f = 0; f < 4; f++) acc[mi][ni][f] = 0.f;

    int arow = tid >> 1, aseg = (tid & 1) * 16;
    int wrow = tid >> 3, wnoff = (tid & 7) * 8;

    uint4 rwa = {0,0,0,0}, rwb = {0,0,0,0};
    float4 rs0, rs1;

    auto cpA = [&](int kt, int buf) {
        long go = (long)arow * K + kt + aseg;
        uint32_t dh = cvta_s(sA_h + buf * 128 * LDA + arow * LDA + aseg);
        uint32_t dl = cvta_s(sA_l + buf * 128 * LDA + arow * LDA + aseg);
        cp16(dh, Ah + go);      cp16(dh + 16, Ah + go + 8);
        cp16(dl, Al + go);      cp16(dl + 16, Al + go + 8);
    };
    auto loadW = [&](int kt) {
        long wo = (long)(kt + wrow) * Nw + bnl + wnoff;
        if (wf == 1) {
            rwa = *(const uint4*)((const int*)W + wo);
            rwb = *(const uint4*)((const int*)W + wo + 4);
        } else if (wf == 0) {
            uint2 r8 = *(const uint2*)((const int8_t*)W + wo);
            rwa.x = r8.x; rwa.y = r8.y;
        } else {
            rwa = *(const uint4*)((const float*)W + wo);
            rwb = *(const uint4*)((const float*)W + wo + 4);
        }
        rs0 = *(const float4*)(S + wo);
        rs1 = *(const float4*)(S + wo + 4);
    };
    auto storeW = [&](int buf) {
        float wd[8];
        if (wf == 1) {
            wd[0] = (float)(int)rwa.x; wd[1] = (float)(int)rwa.y;
            wd[2] = (float)(int)rwa.z; wd[3] = (float)(int)rwa.w;
            wd[4] = (float)(int)rwb.x; wd[5] = (float)(int)rwb.y;
            wd[6] = (float)(int)rwb.z; wd[7] = (float)(int)rwb.w;
        } else if (wf == 0) {
#pragma unroll
            for (int i = 0; i < 4; i++) wd[i]     = (float)(int)(char)(rwa.x >> (8 * i));
#pragma unroll
            for (int i = 0; i < 4; i++) wd[4 + i] = (float)(int)(char)(rwa.y >> (8 * i));
        } else {
            wd[0] = __uint_as_float(rwa.x); wd[1] = __uint_as_float(rwa.y);
            wd[2] = __uint_as_float(rwa.z); wd[3] = __uint_as_float(rwa.w);
            wd[4] = __uint_as_float(rwb.x); wd[5] = __uint_as_float(rwb.y);
            wd[6] = __uint_as_float(rwb.z); wd[7] = __uint_as_float(rwb.w);
        }
        float sc[8] = {rs0.x, rs0.y, rs0.z, rs0.w, rs1.x, rs1.y, rs1.z, rs1.w};
        __nv_bfloat16* bh = sW_h + buf * 32 * LDW + wrow * LDW + wnoff;
        __nv_bfloat16* bl = sW_l + buf * 32 * LDW + wrow * LDW + wnoff;
#pragma unroll
        for (int j = 0; j < 8; j += 2) {
            __nv_bfloat162 lo;
            __nv_bfloat162 hi = split_hi2(wd[j] * sc[j], wd[j + 1] * sc[j + 1], &lo);
            *(__nv_bfloat162*)&bh[j] = hi;
            *(__nv_bfloat162*)&bl[j] = lo;
        }
    };

    int nb = kchunk / 32;
    cpA(kbeg, 0); cp_commit();
    loadW(kbeg);

    for (int it = 0; it < nb; it++) {
        int cur = it & 1;
        storeW(cur);
        cp_wait0();
        __syncthreads();
        if (it + 1 < nb) {
            cpA(kbeg + (it + 1) * 32, cur ^ 1); cp_commit();
            loadW(kbeg + (it + 1) * 32);
        }
        const __nv_bfloat16* aH = sA_h + cur * 128 * LDA;
        const __nv_bfloat16* aL = sA_l + cur * 128 * LDA;
        const __nv_bfloat16* wH = sW_h + cur * 32 * LDW;
        const __nv_bfloat16* wL = sW_l + cur * 32 * LDW;
#pragma unroll
        for (int kk = 0; kk < 32; kk += 16) {
            uint32_t ah[2][4], al[2][4];
#pragma unroll
            for (int mi = 0; mi < 2; mi++) {
                int r = warp_m + mi * 16 + (lane & 15);
                int c = kk + (lane >> 4) * 8;
                ldsm_x4(ah[mi], cvta_s(&aH[r * LDA + c]));
                ldsm_x4(al[mi], cvta_s(&aL[r * LDA + c]));
            }
            uint32_t bh[4][2], bl[4][2];
#pragma unroll
            for (int ni = 0; ni < 4; ni++) {
                int r = kk + (lane & 15);
                int c = warp_n + ni * 8;
                ldsm_x2t(bh[ni], cvta_s(&wH[r * LDW + c]));
                ldsm_x2t(bl[ni], cvta_s(&wL[r * LDW + c]));
            }
#pragma unroll
            for (int mi = 0; mi < 2; mi++)
#pragma unroll
                for (int ni = 0; ni < 4; ni++) {
                    mma_bf16(acc[mi][ni], ah[mi], bh[ni]);
                    mma_bf16(acc[mi][ni], ah[mi], bl[ni]);
                    mma_bf16(acc[mi][ni], al[mi], bh[ni]);
                }
        }
    }

    float* base = P + (long)ks * NROWS * Nout;
    int r0 = lane >> 2, c0 = (lane & 3) * 2;
#pragma unroll
    for (int mi = 0; mi < 2; mi++)
#pragma unroll
        for (int ni = 0; ni < 4; ni++) {
            float* cp = base + (long)(warp_m + mi * 16 + r0) * Nout + bn + warp_n + ni * 8 + c0;
            cp[0] = acc[mi][ni][0];
            cp[1] = acc[mi][ni][1];
            float* cp2 = cp + 8 * (long)Nout;
            cp2[0] = acc[mi][ni][2];
            cp2[1] = acc[mi][ni][3];
        }
}

// ---------------- split-K reduce ----------------------------------------------
__global__ void reduce_splitk(const float* __restrict__ P, float* __restrict__ C,
                              int size4, int nsplit)
{
    int idx = blockIdx.x * blockDim.x + threadIdx.x;
    if (idx >= size4) return;
    const float4* P4 = (const float4*)P;
    float4 s = P4[idx];
    for (int k = 1; k < nsplit; k++) {
        float4 v = P4[(long)k * size4 + idx];
        s.x += v.x; s.y += v.y; s.z += v.z; s.w += v.w;
    }
    ((float4*)C)[idx] = s;
}

// ---------------- fused RoPE (q -> g_qh/g_ql split, k -> g_knew) + step ------
__global__ void rope_fused(const int* __restrict__ step, float* __restrict__ ostep) {
    int idx = blockIdx.x * blockDim.x + threadIdx.x;  // 262144 + 65536
    if (blockIdx.x == 0 && threadIdx.x < BB)
        ostep[threadIdx.x] = (float)(step[threadIdx.x] + TT);
    if (idx < 262144) {
        int row = idx >> 11;
        int rem = idx & 2047;
        int h = rem >> 6, j = rem & 63;
        int b = row >> 4, t = row & 15;
        float x1 = g_pqkv[(long)row * 6144 + h * 128 + j];
        float x2 = g_pqkv[(long)row * 6144 + h * 128 + j + 64];
        float pos = (float)(t + step[b]);
        float invf = (float)exp(-(double)j * 0.14391156831212787);
        float ph = pos * invf;
        float c = cosf(ph), s = sinf(ph);
        float y1 = x1 * c - x2 * s;
        float y2 = x2 * c + x1 * s;
        int kvh = h >> 2, hg = h & 3;
        long orow = ((long)(b * 8 + kvh)) * 64 + hg * 16 + t;
        __nv_bfloat16 h1 = __float2bfloat16(y1);
        __nv_bfloat16 h2 = __float2bfloat16(y2);
        g_qh[orow * 128 + j]      = h1;
        g_ql[orow * 128 + j]      = __float2bfloat16(y1 - __bfloat162float(h1));
        g_qh[orow * 128 + j + 64] = h2;
        g_ql[orow * 128 + j + 64] = __float2bfloat16(y2 - __bfloat162float(h2));
    } else {
        int i2 = idx - 262144;     // 65536 k elems
        int row = i2 >> 9;
        int rem = i2 & 511;
        int h = rem >> 6, j = rem & 63;
        int b = row >> 4, t = row & 15;
        float x1 = g_pqkv[(long)row * 6144 + 4096 + h * 128 + j];
        float x2 = g_pqkv[(long)row * 6144 + 4096 + h * 128 + j + 64];
        int pos = t + step[b];
        float invf = (float)exp(-(double)j * 0.14391156831212787);
        float ph = (float)pos * invf;
        float c = cosf(ph), s = sinf(ph);
        float* dst = g_knew + (long)row * 1024 + h * 128;
        dst[j]      = x1 * c - x2 * s;
        dst[j + 64] = x2 * c + x1 * s;
    }
}

// ---------------- final scatter of new rows into kc/vc ------------------------
__global__ void scatter_new(const int* __restrict__ step,
                            float* __restrict__ kc, float* __restrict__ vc) {
    int idx = blockIdx.x * blockDim.x + threadIdx.x;   // 128*1024
    int row = idx >> 10;
    int rem = idx & 1023;
    int b = row >> 4, t = row & 15;
    int h = rem >> 7, d = rem & 127;
    long gi = (((long)b * MM + (step[b] + t)) * HK + h) * DKH + d;
    kc[gi] = g_knew[idx];
    vc[gi] = g_pqkv[(long)row * 6144 + 5120 + rem];
}

// ---------------- Tensor-core attention (64-key chunks, 2 blocks/SM) ---------
// P buffers alias the Q buffers (Q dead after QK; syncs protect the alias).
#define LDQ 136
#define LDK 136
#define LDV 136
#define LDP 72
#define ATTN_SMEM ((3 * 2 * 64 * 136) * 2 + 256)
__global__ __launch_bounds__(256, 2) void attn_tc(
    const float* __restrict__ mem_k, const float* __restrict__ mem_v,
    const int* __restrict__ step)
{
    extern __shared__ char smraw[];
    __nv_bfloat16* sQh = (__nv_bfloat16*)smraw;          // 64 x LDQ
    __nv_bfloat16* sQl = sQh + 64 * LDQ;
    __nv_bfloat16* sKh = sQl + 64 * LDQ;                 // 64 x LDK
    __nv_bfloat16* sKl = sKh + 64 * LDK;
    __nv_bfloat16* sVh = sKl + 64 * LDK;                 // 64 x LDV
    __nv_bfloat16* sVl = sVh + 64 * LDV;
    __nv_bfloat16* sPh = (__nv_bfloat16*)smraw;          // alias Q region
    __nv_bfloat16* sPl = sPh + 64 * LDP;
    float* sRow = (float*)(sVl + 64 * LDV);

    int chunk = blockIdx.x, kvh = blockIdx.y, b = blockIdx.z;
    int tid = threadIdx.x;
    int wid = tid >> 5, lane = tid & 31;
    int j0 = chunk * 64;
    int stepb = step[b];
    int nstep = stepb + TT;
    if (j0 >= nstep) return;

    if (tid < 64) sRow[tid] = 0.f;

    // ---- stage Q (64 x 128) ----
    {
        const uint4* qh = (const uint4*)(g_qh + ((long)(b * 8 + kvh)) * 64 * 128);
        const uint4* ql = (const uint4*)(g_ql + ((long)(b * 8 + kvh)) * 64 * 128);
        for (int i = tid; i < 1024; i += 256) {
            int qi = i >> 4, seg = (i & 15) * 8;
            *(uint4*)&sQh[qi * LDQ + seg] = qh[i];
            *(uint4*)&sQl[qi * LDQ + seg] = ql[i];
        }
    }
    // ---- stage K rows (64 x 128) + split ----
    {
        int jj = tid >> 2, dh = (tid & 3) * 32;
        int pos = j0 + jj;
        int rel = pos - stepb;
        const float* kp = (rel >= 0 && rel < TT)
            ? g_knew + ((long)(b * 16 + rel)) * 1024 + kvh * 128 + dh
            : mem_k + (((long)b * MM + pos) * HK + kvh) * DKH + dh;
#pragma unroll
        for (int i = 0; i < 8; i++) {
            float4 v = *(const float4*)(kp + i * 4);
            float x[4] = {v.x, v.y, v.z, v.w};
#pragma unroll
            for (int u = 0; u < 4; u += 2) {
                __nv_bfloat162 lo;
                __nv_bfloat162 hi = split_hi2(x[u], x[u + 1], &lo);
                int d = dh + i * 4 + u;
                *(__nv_bfloat162*)&sKh[jj * LDK + d] = hi;
                *(__nv_bfloat162*)&sKl[jj * LDK + d] = lo;
            }
        }
    }
    // ---- stage V rows (64 x 128) + split ----
    {
        int jj = tid >> 2, dh = (tid & 3) * 32;
        int pos = j0 + jj;
        int rel = pos - stepb;
        const float* vp = (rel >= 0 && rel < TT)
            ? g_pqkv + ((long)(b * 16 + rel)) * 6144 + 5120 + kvh * 128 + dh
            : mem_v + (((long)b * MM + pos) * HK + kvh) * DKH + dh;
#pragma unroll
        for (int i = 0; i < 8; i++) {
            float4 v = *(const float4*)(vp + i * 4);
            float x[4] = {v.x, v.y, v.z, v.w};
#pragma unroll
            for (int u = 0; u < 4; u += 2) {
                __nv_bfloat162 lo;
                __nv_bfloat162 hi = split_hi2(x[u], x[u + 1], &lo);
                int d = dh + i * 4 + u;
                *(__nv_bfloat162*)&sVh[jj * LDV + d] = hi;
                *(__nv_bfloat162*)&sVl[jj * LDV + d] = lo;
            }
        }
    }
    __syncthreads();

    int warp_m = (wid >> 2) * 32;          // 2 m-groups of 32 q rows
    int warp_nq = (wid & 3) * 16;          // 4 n-groups of 16 key cols (QK)
    int warp_nv = (wid & 3) * 32;          // 4 n-groups of 32 d cols (PV)

    // ---- QK^T: S[64 q][64 keys] ----
    float acc[2][2][4];
#pragma unroll
    for (int mi = 0; mi < 2; mi++)
#pragma unroll
        for (int ni = 0; ni < 2; ni++)
#pragma unroll
            for (int f = 0; f < 4; f++) acc[mi][ni][f] = 0.f;

#pragma unroll
    for (int kk = 0; kk < 128; kk += 16) {
        uint32_t ah[2][4], al[2][4];
#pragma unroll
        for (int mi = 0; mi < 2; mi++) {
            int r = warp_m + mi * 16 + (lane & 15);
            int c = kk + (lane >> 4) * 8;
            ldsm_x4(ah[mi], cvta_s(&sQh[r * LDQ + c]));
            ldsm_x4(al[mi], cvta_s(&sQl[r * LDQ + c]));
        }
        uint32_t bh[2][2], bl[2][2];
#pragma unroll
        for (int ni = 0; ni < 2; ni++) {
            int nrow = warp_nq + ni * 8 + (lane & 7);
            int kcol = kk + ((lane >> 3) & 1) * 8;
            ldsm_x2(bh[ni], cvta_s(&sKh[nrow * LDK + kcol]));
            ldsm_x2(bl[ni], cvta_s(&sKl[nrow * LDK + kcol]));
        }
#pragma unroll
        for (int mi = 0; mi < 2; mi++)
#pragma unroll
            for (int ni = 0; ni < 2; ni++) {
                mma_bf16(acc[mi][ni], ah[mi], bh[ni]);
                mma_bf16(acc[mi][ni], ah[mi], bl[ni]);
                mma_bf16(acc[mi][ni], al[mi], bh[ni]);
            }
    }
    __syncthreads();     // all warps done reading Q before P overwrites it

    // ---- capped softmax numerator -> P (aliased) ----
#pragma unroll
    for (int mi = 0; mi < 2; mi++) {
        int r_lo = warp_m + mi * 16 + (lane >> 2);
        int r_hi = r_lo + 8;
        float s0 = 0.f, s1 = 0.f;
#pragma unroll
        for (int ni = 0; ni < 2; ni++) {
            int c0 = warp_nq + ni * 8 + (lane & 3) * 2;
            float p[4];
#pragma unroll
            for (int f = 0; f < 4; f++) {
                int jg = j0 + c0 + (f & 1);
                float u = acc[mi][ni][f] * (MULT / 30.f);
                float t2 = __expf(-2.f * fabsf(u));
                float th = __fdividef(1.f - t2, 1.f + t2);
                th = copysignf(th, u);
                p[f] = (jg < nstep) ? __expf(30.f * th) : 0.f;
            }
            s0 += p[0] + p[1];
            s1 += p[2] + p[3];
            __nv_bfloat162 lo;
            __nv_bfloat162 hi = split_hi2(p[0], p[1], &lo);
            *(__nv_bfloat162*)&sPh[r_lo * LDP + c0] = hi;
            *(__nv_bfloat162*)&sPl[r_lo * LDP + c0] = lo;
            hi = split_hi2(p[2], p[3], &lo);
            *(__nv_bfloat162*)&sPh[r_hi * LDP + c0] = hi;
            *(__nv_bfloat162*)&sPl[r_hi * LDP + c0] = lo;
        }
        s0 += __shfl_xor_sync(0xffffffff, s0, 1);
        s0 += __shfl_xor_sync(0xffffffff, s0, 2);
        s1 += __shfl_xor_sync(0xffffffff, s1, 1);
        s1 += __shfl_xor_sync(0xffffffff, s1, 2);
        if ((lane & 3) == 0) {
            atomicAdd(&sRow[r_lo], s0);
            atomicAdd(&sRow[r_hi], s1);
        }
    }
    __syncthreads();

    int pbase = (b * 8 + kvh) * 64 + chunk;
    if (tid < 64) g_pl[pbase * 64 + tid] = sRow[tid];

    // ---- PV: out[64 q][128 d] = P[64 x 64] @ V[64 x 128] ----
    float oacc[2][4][4];
#pragma unroll
    for (int mi = 0; mi < 2; mi++)
#pragma unroll
        for (int ni = 0; ni < 4; ni++)
#pragma unroll
            for (int f = 0; f < 4; f++) oacc[mi][ni][f] = 0.f;

#pragma unroll
    for (int kk = 0; kk < 64; kk += 16) {
        uint32_t ph[2][4], pl[2][4];
#pragma unroll
        for (int mi = 0; mi < 2; mi++) {
            int r = warp_m + mi * 16 + (lane & 15);
            int c = kk + (lane >> 4) * 8;
            ldsm_x4(ph[mi], cvta_s(&sPh[r * LDP + c]));
            ldsm_x4(pl[mi], cvta_s(&sPl[r * LDP + c]));
        }
        uint32_t vh[4][2], vl[4][2];
#pragma unroll
        for (int ni = 0; ni < 4; ni++) {
            int r = kk + (lane & 15);
            int c = warp_nv + ni * 8;
            ldsm_x2t(vh[ni], cvta_s(&sVh[r * LDV + c]));
            ldsm_x2t(vl[ni], cvta_s(&sVl[r * LDV + c]));
        }
#pragma unroll
        for (int mi = 0; mi < 2; mi++)
#pragma unroll
            for (int ni = 0; ni < 4; ni++) {
                mma_bf16(oacc[mi][ni], ph[mi], vh[ni]);
                mma_bf16(oacc[mi][ni], ph[mi], vl[ni]);
                mma_bf16(oacc[mi][ni], pl[mi], vh[ni]);
            }
    }

    float* dst = &g_pacc[(long)pbase * 8192];
#pragma unroll
    for (int mi = 0; mi < 2; mi++) {
        int r_lo = warp_m + mi * 16 + (lane >> 2);
#pragma unroll
        for (int ni = 0; ni < 4; ni++) {
            int d0 = warp_nv + ni * 8 + (lane & 3) * 2;
            *(float2*)&dst[r_lo * 128 + d0] = make_float2(oacc[mi][ni][0], oacc[mi][ni][1]);
            *(float2*)&dst[(r_lo + 8) * 128 + d0] = make_float2(oacc[mi][ni][2], oacc[mi][ni][3]);
        }
    }
}

// ---------------- Combine partials -> split bf16 A for O-proj ----------------
__global__ void combine_kernel(const int* __restrict__ step) {
    int blk = blockIdx.x;
    int qi = blk & 63;
    int bk = blk >> 6;
    int kvh = bk & 7, b = bk >> 3;
    int d = threadIdx.x;           // 128
    int nstep = step[b] + TT;
    int nch = (nstep + 63) >> 6;
    if (nch > 64) nch = 64;
    float asum = 0.f, lsum = 0.f;
    int base = bk * 64;
    for (int c = 0; c < nch; c++)
        asum += g_pacc[(long)(base + c) * 8192 + qi * 128 + d];
    for (int c = 0; c < nch; c++)
        lsum += g_pl[(base + c) * 64 + qi];
    int t = qi & 15, hg = qi >> 4;
    float val = asum / lsum;
    long oidx = (((long)(b * 16 + t)) * 32 + kvh * 4 + hg) * 128 + d;
    __nv_bfloat16 h = __float2bfloat16(val);
    g_ah[oidx] = h;
    g_al[oidx] = __float2bfloat16(val - __bfloat162float(h));
}

// ---------------- launch ------------------------------------------------------
extern "C" void kernel_launch(void* const* d_in, const int* in_sizes, int n_in,
                              void* d_out, int out_size)
{
    const float*   query = (const float*)d_in[0];
    const float*   keyx  = (const float*)d_in[1];
    const float*   value = (const float*)d_in[2];
    const float*   mem_k = (const float*)d_in[4];
    const float*   mem_v = (const float*)d_in[5];
    const int*     step  = (const int*)d_in[6];
    const void*    wq = d_in[7];
    const float*   sq = (const float*)d_in[8];
    const void*    wk = d_in[9];
    const float*   sk = (const float*)d_in[10];
    const void*    wv = d_in[11];
    const float*   sv = (const float*)d_in[12];
    const void*    wo = d_in[13];
    const float*   so = (const float*)d_in[14];

    float* out = (float*)d_out;
    float* kc    = out + OFF_KC;
    float* vc    = out + OFF_VC;
    float* ostep = out + OFF_STEP;

    // Side stream (created once) for the independent full cache copy.
    static cudaStream_t s1 = nullptr;
    static cudaEvent_t ev0 = nullptr, ev1 = nullptr;
    static bool sok = false;
    if (!s1) {
        sok = (cudaStreamCreateWithFlags(&s1, cudaStreamNonBlocking) == cudaSuccess) &&
              (cudaEventCreateWithFlags(&ev0, cudaEventDisableTiming) == cudaSuccess) &&
              (cudaEventCreateWithFlags(&ev1, cudaEventDisableTiming) == cudaSuccess);
    }

    if (sok) {
        cudaEventRecord(ev0, 0);
        cudaStreamWaitEvent(s1, ev0, 0);
        copy_cache<<<512, 256, 0, s1>>>((const uint4*)mem_k, (uint4*)kc,
                                        (const uint4*)mem_v, (uint4*)vc);
        cudaEventRecord(ev1, s1);
    } else {
        copy_cache<<<512, 256>>>((const uint4*)mem_k, (uint4*)kc,
                                 (const uint4*)mem_v, (uint4*)vc);
    }

    detect_wdtype<<<1, 256>>>(wq);

    float *pqkv, *part;
    __nv_bfloat16 *ah, *al;
    cudaGetSymbolAddress((void**)&pqkv, g_pqkv);
    cudaGetSymbolAddress((void**)&part, g_part);
    cudaGetSymbolAddress((void**)&ah, g_ah);
    cudaGetSymbolAddress((void**)&al, g_al);

    cudaFuncSetAttribute(gemm_tc, cudaFuncAttributeMaxDynamicSharedMemorySize, GEMM_SMEM);
    cudaFuncSetAttribute(attn_tc, cudaFuncAttributeMaxDynamicSharedMemorySize, ATTN_SMEM);

    // Fused QKV projection (R13 config)
    presplit_all<<<1536, 1024>>>(query, keyx, value);
    gemm_tc<<<dim3(96, 8), 256, GEMM_SMEM>>>(ah, al, wq, sq, wk, sk, wv, sv,
                                             part, 0, 512);
    reduce_splitk<<<768, 256>>>(part, pqkv, 196608, 8);

    // RoPE + new_step
    rope_fused<<<1280, 256>>>(step, ostep);

    // Tensor-core attention: 64-key chunks, 2 blocks/SM
    attn_tc<<<dim3(64, 8, 8), 256, ATTN_SMEM>>>(mem_k, mem_v, step);
    combine_kernel<<<4096, 128>>>(step);

    // Output projection (R13 config: 16-way split-K)
    gemm_tc<<<dim3(64, 16), 256, GEMM_SMEM>>>(ah, al, wo, so, wo, so, wo, so,
                                              part, 1, 256);
    reduce_splitk<<<512, 256>>>(part, out, 131072, 16);

    // Join copy stream, then scatter the 16 new rows into kc/vc
    if (sok) cudaStreamWaitEvent(0, ev1, 0);
    scatter_new<<<512, 256>>>(step, kc, vc);
}

// round 16
// speedup vs baseline: 1.1218x; 1.0816x over previous
#include <cuda_runtime.h>
#include <cuda_bf16.h>
#include <cstdint>
#include <cmath>

// Problem constants
#define BB 8
#define TT 16
#define DD 4096
#define MM 4096
#define HQ 32
#define HK 8
#define DKH 128
#define NROWS 128      // B*T
#define MULT 0.08838834764831845f

// Output layout (fp32 elements): out | kc | vc | new_step
#define OFF_KC   (524288)
#define OFF_VC   (OFF_KC + 33554432)
#define OFF_STEP (OFF_VC + 33554432)

// ---------------- scratch (device globals; no allocation allowed) -------------
__device__ float g_pqkv[NROWS * 6144];      // fused qkv proj (q|k|v cols)
__device__ float g_knew[NROWS * 1024];      // rope'd k (new rows)
__device__ __align__(16) __nv_bfloat16 g_qh[8 * 8 * 64 * 128];  // rope'd q hi
__device__ __align__(16) __nv_bfloat16 g_ql[8 * 8 * 64 * 128];  // rope'd q lo
__device__ __align__(16) __nv_bfloat16 g_ah[3 * NROWS * 4096];  // pre-split A hi (q|k|v)
__device__ __align__(16) __nv_bfloat16 g_al[3 * NROWS * 4096];  // pre-split A lo
__device__ float g_part[8388608];           // split-K partials
__device__ float g_pacc[1024L * 64 * 128];  // partial PV accumulators (33.5MB)
__device__ float g_pl[1024 * 64];           // partial softmax denominators
__device__ int   g_wflag;                   // 0=int8 packed, 1=int32, 2=float32

// ---------------- weight dtype detection -------------------------------------
__global__ void detect_wdtype(const void* __restrict__ w) {
    int tid = threadIdx.x;
    const int* wi = (const int*)w;
    int v = wi[tid];
    bool small = (v >= -127 && v <= 127);
    int all_small = __syncthreads_and((int)small);
    if (all_small) { if (tid == 0) g_wflag = 1; return; }
    float fv = __int_as_float(v);
    bool isf = isfinite(fv) && fabsf(fv) <= 127.0f && fv == rintf(fv);
    int all_f = __syncthreads_and((int)isf);
    if (tid == 0) g_wflag = all_f ? 2 : 0;
}

// ---------------- SM-path cache copy (side stream) ---------------------------
__global__ void copy_cache(const uint4* __restrict__ src_k, uint4* __restrict__ dst_k,
                           const uint4* __restrict__ src_v, uint4* __restrict__ dst_v)
{
    const long n4 = 8388608;   // 33554432 floats / 4
    long stride = (long)gridDim.x * blockDim.x;
    for (long i = (long)blockIdx.x * blockDim.x + threadIdx.x; i < n4; i += stride) {
        dst_k[i] = src_k[i];
        dst_v[i] = src_v[i];
    }
}

// ---------------- tensor-core / async helpers ---------------------------------
__device__ __forceinline__ uint32_t cvta_s(const void* p) {
    return (uint32_t)__cvta_generic_to_shared(p);
}
__device__ __forceinline__ void ldsm_x4(uint32_t* r, uint32_t a) {
    asm volatile("ldmatrix.sync.aligned.m8n8.x4.shared.b16 {%0,%1,%2,%3}, [%4];"
        : "=r"(r[0]), "=r"(r[1]), "=r"(r[2]), "=r"(r[3]) : "r"(a));
}
__device__ __forceinline__ void ldsm_x2t(uint32_t* r, uint32_t a) {
    asm volatile("ldmatrix.sync.aligned.m8n8.x2.trans.shared.b16 {%0,%1}, [%2];"
        : "=r"(r[0]), "=r"(r[1]) : "r"(a));
}
__device__ __forceinline__ void ldsm_x2(uint32_t* r, uint32_t a) {
    asm volatile("ldmatrix.sync.aligned.m8n8.x2.shared.b16 {%0,%1}, [%2];"
        : "=r"(r[0]), "=r"(r[1]) : "r"(a));
}
__device__ __forceinline__ void mma_bf16(float* c, const uint32_t* a, const uint32_t* b) {
    asm volatile("mma.sync.aligned.m16n8k16.row.col.f32.bf16.bf16.f32 "
        "{%0,%1,%2,%3}, {%4,%5,%6,%7}, {%8,%9}, {%0,%1,%2,%3};"
        : "+f"(c[0]), "+f"(c[1]), "+f"(c[2]), "+f"(c[3])
        : "r"(a[0]), "r"(a[1]), "r"(a[2]), "r"(a[3]), "r"(b[0]), "r"(b[1]));
}
__device__ __forceinline__ void cp16(uint32_t dst, const void* src) {
    asm volatile("cp.async.cg.shared.global [%0], [%1], 16;" :: "r"(dst), "l"(src));
}
__device__ __forceinline__ void cp_commit() {
    asm volatile("cp.async.commit_group;");
}
__device__ __forceinline__ void cp_wait0() {
    asm volatile("cp.async.wait_group 0;");
}
__device__ __forceinline__ __nv_bfloat162 split_hi2(float a, float b, __nv_bfloat162* lo) {
    __nv_bfloat16 h0 = __float2bfloat16(a);
    __nv_bfloat16 h1 = __float2bfloat16(b);
    *lo = __halves2bfloat162(__float2bfloat16(a - __bfloat162float(h0)),
                             __float2bfloat16(b - __bfloat162float(h1)));
    return __halves2bfloat162(h0, h1);
}

// ---------------- A pre-split (q|k|v fused) -----------------------------------
__global__ void presplit_all(const float* __restrict__ q,
                             const float* __restrict__ k,
                             const float* __restrict__ v) {
    int idx = blockIdx.x * blockDim.x + threadIdx.x;   // 3*524288
    int sel = idx >> 19;
    int off = idx & 524287;
    const float* src = (sel == 0) ? q : (sel == 1) ? k : v;
    float a = src[off];
    __nv_bfloat16 h = __float2bfloat16(a);
    g_ah[idx] = h;
    g_al[idx] = __float2bfloat16(a - __bfloat162float(h));
}

// ---------------- pipelined split-bf16 tensor-core GEMM -----------------------
// mode 0: fused QKV (Nout=6144), mode 1: single (Nout=4096)
#define LDA 40
#define LDW 72
#define GEMM_SMEM ((4 * 128 * LDA + 4 * 32 * LDW) * 2)
__global__ __launch_bounds__(256, 3) void gemm_tc(
    const __nv_bfloat16* __restrict__ AhBase, const __nv_bfloat16* __restrict__ AlBase,
    const void* __restrict__ W0, const float* __restrict__ S0,
    const void* __restrict__ W1, const float* __restrict__ S1,
    const void* __restrict__ W2, const float* __restrict__ S2,
    float* __restrict__ P, int mode, int kchunk)
{
    extern __shared__ __nv_bfloat16 smg[];
    __nv_bfloat16* sA_h = smg;                     // [2][128*LDA]
    __nv_bfloat16* sA_l = smg + 2 * 128 * LDA;
    __nv_bfloat16* sW_h = smg + 4 * 128 * LDA;     // [2][32*LDW]
    __nv_bfloat16* sW_l = smg + 4 * 128 * LDA + 2 * 32 * LDW;

    const int K = 4096;
    int bn = blockIdx.x * 64;
    int ks = blockIdx.y;
    int kbeg = ks * kchunk;
    int tid = threadIdx.x;
    int wid = tid >> 5, lane = tid & 31;
    int wf = g_wflag;

    const void* W; const float* S; int Nw, bnl, Nout, asel;
    if (mode == 0) {
        Nout = 6144;
        if (bn < 4096)      { W = W0; S = S0; Nw = 4096; bnl = bn;        asel = 0; }
        else if (bn < 5120) { W = W1; S = S1; Nw = 1024; bnl = bn - 4096; asel = 1; }
        else                { W = W2; S = S2; Nw = 1024; bnl = bn - 5120; asel = 2; }
    } else { W = W0; S = S0; Nw = 4096; bnl = bn; Nout = 4096; asel = 0; }
    const __nv_bfloat16* Ah = AhBase + (long)asel * 524288;
    const __nv_bfloat16* Al = AlBase + (long)asel * 524288;

    int warp_m = (wid >> 1) * 32;
    int warp_n = (wid & 1) * 32;

    float acc[2][4][4];
#pragma unroll
    for (int mi = 0; mi < 2; mi++)
#pragma unroll
        for (int ni = 0; ni < 4; ni++)
#pragma unroll
            for (int f = 0; f < 4; f++) acc[mi][ni][f] = 0.f;

    int arow = tid >> 1, aseg = (tid & 1) * 16;
    int wrow = tid >> 3, wnoff = (tid & 7) * 8;

    uint4 rwa = {0,0,0,0}, rwb = {0,0,0,0};
    float4 rs0, rs1;

    auto cpA = [&](int kt, int buf) {
        long go = (long)arow * K + kt + aseg;
        uint32_t dh = cvta_s(sA_h + buf * 128 * LDA + arow * LDA + aseg);
        uint32_t dl = cvta_s(sA_l + buf * 128 * LDA + arow * LDA + aseg);
        cp16(dh, Ah + go);      cp16(dh + 16, Ah + go + 8);
        cp16(dl, Al + go);      cp16(dl + 16, Al + go + 8);
    };
    auto loadW = [&](int kt) {
        long wo = (long)(kt + wrow) * Nw + bnl + wnoff;
        if (wf == 1) {
            rwa = *(const uint4*)((const int*)W + wo);
            rwb = *(const uint4*)((const int*)W + wo + 4);
        } else if (wf == 0) {
            uint2 r8 = *(const uint2*)((const int8_t*)W + wo);
            rwa.x = r8.x; rwa.y = r8.y;
        } else {
            rwa = *(const uint4*)((const float*)W + wo);
            rwb = *(const uint4*)((const float*)W + wo + 4);
        }
        rs0 = *(const float4*)(S + wo);
        rs1 = *(const float4*)(S + wo + 4);
    };
    auto storeW = [&](int buf) {
        float wd[8];
        if (wf == 1) {
            wd[0] = (float)(int)rwa.x; wd[1] = (float)(int)rwa.y;
            wd[2] = (float)(int)rwa.z; wd[3] = (float)(int)rwa.w;
            wd[4] = (float)(int)rwb.x; wd[5] = (float)(int)rwb.y;
            wd[6] = (float)(int)rwb.z; wd[7] = (float)(int)rwb.w;
        } else if (wf == 0) {
#pragma unroll
            for (int i = 0; i < 4; i++) wd[i]     = (float)(int)(char)(rwa.x >> (8 * i));
#pragma unroll
            for (int i = 0; i < 4; i++) wd[4 + i] = (float)(int)(char)(rwa.y >> (8 * i));
        } else {
            wd[0] = __uint_as_float(rwa.x); wd[1] = __uint_as_float(rwa.y);
            wd[2] = __uint_as_float(rwa.z); wd[3] = __uint_as_float(rwa.w);
            wd[4] = __uint_as_float(rwb.x); wd[5] = __uint_as_float(rwb.y);
            wd[6] = __uint_as_float(rwb.z); wd[7] = __uint_as_float(rwb.w);
        }
        float sc[8] = {rs0.x, rs0.y, rs0.z, rs0.w, rs1.x, rs1.y, rs1.z, rs1.w};
        __nv_bfloat16* bh = sW_h + buf * 32 * LDW + wrow * LDW + wnoff;
        __nv_bfloat16* bl = sW_l + buf * 32 * LDW + wrow * LDW + wnoff;
#pragma unroll
        for (int j = 0; j < 8; j += 2) {
            __nv_bfloat162 lo;
            __nv_bfloat162 hi = split_hi2(wd[j] * sc[j], wd[j + 1] * sc[j + 1], &lo);
            *(__nv_bfloat162*)&bh[j] = hi;
            *(__nv_bfloat162*)&bl[j] = lo;
        }
    };

    int nb = kchunk / 32;
    cpA(kbeg, 0); cp_commit();
    loadW(kbeg);

    for (int it = 0; it < nb; it++) {
        int cur = it & 1;
        storeW(cur);
        cp_wait0();
        __syncthreads();
        if (it + 1 < nb) {
            cpA(kbeg + (it + 1) * 32, cur ^ 1); cp_commit();
            loadW(kbeg + (it + 1) * 32);
        }
        const __nv_bfloat16* aH = sA_h + cur * 128 * LDA;
        const __nv_bfloat16* aL = sA_l + cur * 128 * LDA;
        const __nv_bfloat16* wH = sW_h + cur * 32 * LDW;
        const __nv_bfloat16* wL = sW_l + cur * 32 * LDW;
#pragma unroll
        for (int kk = 0; kk < 32; kk += 16) {
            uint32_t ah[2][4], al[2][4];
#pragma unroll
            for (int mi = 0; mi < 2; mi++) {
                int r = warp_m + mi * 16 + (lane & 15);
                int c = kk + (lane >> 4) * 8;
                ldsm_x4(ah[mi], cvta_s(&aH[r * LDA + c]));
                ldsm_x4(al[mi], cvta_s(&aL[r * LDA + c]));
            }
            uint32_t bh[4][2], bl[4][2];
#pragma unroll
            for (int ni = 0; ni < 4; ni++) {
                int r = kk + (lane & 15);
                int c = warp_n + ni * 8;
                ldsm_x2t(bh[ni], cvta_s(&wH[r * LDW + c]));
                ldsm_x2t(bl[ni], cvta_s(&wL[r * LDW + c]));
            }
#pragma unroll
            for (int mi = 0; mi < 2; mi++)
#pragma unroll
                for (int ni = 0; ni < 4; ni++) {
                    mma_bf16(acc[mi][ni], ah[mi], bh[ni]);
                    mma_bf16(acc[mi][ni], ah[mi], bl[ni]);
                    mma_bf16(acc[mi][ni], al[mi], bh[ni]);
                }
        }
    }

    float* base = P + (long)ks * NROWS * Nout;
    int r0 = lane >> 2, c0 = (lane & 3) * 2;
#pragma unroll
    for (int mi = 0; mi < 2; mi++)
#pragma unroll
        for (int ni = 0; ni < 4; ni++) {
            float* cp = base + (long)(warp_m + mi * 16 + r0) * Nout + bn + warp_n + ni * 8 + c0;
            cp[0] = acc[mi][ni][0];
            cp[1] = acc[mi][ni][1];
            float* cp2 = cp + 8 * (long)Nout;
            cp2[0] = acc[mi][ni][2];
            cp2[1] = acc[mi][ni][3];
        }
}

// ---------------- split-K reduce ----------------------------------------------
__global__ void reduce_splitk(const float* __restrict__ P, float* __restrict__ C,
                              int size4, int nsplit)
{
    int idx = blockIdx.x * blockDim.x + threadIdx.x;
    if (idx >= size4) return;
    const float4* P4 = (const float4*)P;
    float4 s = P4[idx];
    for (int k = 1; k < nsplit; k++) {
        float4 v = P4[(long)k * size4 + idx];
        s.x += v.x; s.y += v.y; s.z += v.z; s.w += v.w;
    }
    ((float4*)C)[idx] = s;
}

// ---------------- fused RoPE (q -> g_qh/g_ql split, k -> g_knew) + step ------
__global__ void rope_fused(const int* __restrict__ step, float* __restrict__ ostep) {
    int idx = blockIdx.x * blockDim.x + threadIdx.x;  // 262144 + 65536
    if (blockIdx.x == 0 && threadIdx.x < BB)
        ostep[threadIdx.x] = (float)(step[threadIdx.x] + TT);
    if (idx < 262144) {
        int row = idx >> 11;
        int rem = idx & 2047;
        int h = rem >> 6, j = rem & 63;
        int b = row >> 4, t = row & 15;
        float x1 = g_pqkv[(long)row * 6144 + h * 128 + j];
        float x2 = g_pqkv[(long)row * 6144 + h * 128 + j + 64];
        float pos = (float)(t + step[b]);
        float invf = (float)exp(-(double)j * 0.14391156831212787);
        float ph = pos * invf;
        float c = cosf(ph), s = sinf(ph);
        float y1 = x1 * c - x2 * s;
        float y2 = x2 * c + x1 * s;
        int kvh = h >> 2, hg = h & 3;
        long orow = ((long)(b * 8 + kvh)) * 64 + hg * 16 + t;
        __nv_bfloat16 h1 = __float2bfloat16(y1);
        __nv_bfloat16 h2 = __float2bfloat16(y2);
        g_qh[orow * 128 + j]      = h1;
        g_ql[orow * 128 + j]      = __float2bfloat16(y1 - __bfloat162float(h1));
        g_qh[orow * 128 + j + 64] = h2;
        g_ql[orow * 128 + j + 64] = __float2bfloat16(y2 - __bfloat162float(h2));
    } else {
        int i2 = idx - 262144;     // 65536 k elems
        int row = i2 >> 9;
        int rem = i2 & 511;
        int h = rem >> 6, j = rem & 63;
        int b = row >> 4, t = row & 15;
        float x1 = g_pqkv[(long)row * 6144 + 4096 + h * 128 + j];
        float x2 = g_pqkv[(long)row * 6144 + 4096 + h * 128 + j + 64];
        int pos = t + step[b];
        float invf = (float)exp(-(double)j * 0.14391156831212787);
        float ph = (float)pos * invf;
        float c = cosf(ph), s = sinf(ph);
        float* dst = g_knew + (long)row * 1024 + h * 128;
        dst[j]      = x1 * c - x2 * s;
        dst[j + 64] = x2 * c + x1 * s;
    }
}

// ---------------- final scatter of new rows into kc/vc ------------------------
__global__ void scatter_new(const int* __restrict__ step,
                            float* __restrict__ kc, float* __restrict__ vc) {
    int idx = blockIdx.x * blockDim.x + threadIdx.x;   // 128*1024
    int row = idx >> 10;
    int rem = idx & 1023;
    int b = row >> 4, t = row & 15;
    int h = rem >> 7, d = rem & 127;
    long gi = (((long)b * MM + (step[b] + t)) * HK + h) * DKH + d;
    kc[gi] = g_knew[idx];
    vc[gi] = g_pqkv[(long)row * 6144 + 5120 + rem];
}

// ---------------- Tensor-core attention: 4x64-key chunks per block -----------
// Register-accumulated PV across chunks; K/V share one smem buffer.
#define LDQ 136
#define LDKV 136
#define LDP 72
#define ATTN_SMEM ((2*64*LDQ + 2*64*LDKV + 2*64*LDP) * 2 + 256)
__global__ __launch_bounds__(256, 2) void attn_tc(
    const float* __restrict__ mem_k, const float* __restrict__ mem_v,
    const int* __restrict__ step)
{
    extern __shared__ char smraw[];
    __nv_bfloat16* sQh = (__nv_bfloat16*)smraw;            // 64 x LDQ
    __nv_bfloat16* sQl = sQh + 64 * LDQ;
    __nv_bfloat16* sKVh = sQl + 64 * LDQ;                  // 64 x LDKV (K then V)
    __nv_bfloat16* sKVl = sKVh + 64 * LDKV;
    __nv_bfloat16* sPh = sKVl + 64 * LDKV;                 // 64 x LDP
    __nv_bfloat16* sPl = sPh + 64 * LDP;
    float* sRow = (float*)(sPl + 64 * LDP);

    int blkc = blockIdx.x, kvh = blockIdx.y, b = blockIdx.z;
    int tid = threadIdx.x;
    int wid = tid >> 5, lane = tid & 31;
    int j0 = blkc * 256;
    int stepb = step[b];
    int nstep = stepb + TT;
    if (j0 >= nstep) return;

    if (tid < 64) sRow[tid] = 0.f;

    // ---- stage Q (once, reused for 4 chunks) ----
    {
        const uint4* qh = (const uint4*)(g_qh + ((long)(b * 8 + kvh)) * 64 * 128);
        const uint4* ql = (const uint4*)(g_ql + ((long)(b * 8 + kvh)) * 64 * 128);
        for (int i = tid; i < 1024; i += 256) {
            int qi = i >> 4, seg = (i & 15) * 8;
            *(uint4*)&sQh[qi * LDQ + seg] = qh[i];
            *(uint4*)&sQl[qi * LDQ + seg] = ql[i];
        }
    }

    int warp_m = (wid >> 2) * 32;
    int warp_nq = (wid & 3) * 16;
    int warp_nv = (wid & 3) * 32;

    int jj = tid >> 2, dh = (tid & 3) * 32;   // staging coords (64 rows x 128 d)

    float oacc[2][4][4];
#pragma unroll
    for (int mi = 0; mi < 2; mi++)
#pragma unroll
        for (int ni = 0; ni < 4; ni++)
#pragma unroll
            for (int f = 0; f < 4; f++) oacc[mi][ni][f] = 0.f;

    for (int c4 = 0; c4 < 4; c4++) {
        int jb = j0 + c4 * 64;
        if (jb >= nstep) break;

        int pos = jb + jj;
        int rel = pos - stepb;
        bool isnew = (rel >= 0 && rel < TT);
        long coff = (((long)b * MM + pos) * HK + kvh) * DKH + dh;

        __syncthreads();    // prev PV done reading KV; Q staged (iter 0)

        // ---- stage K into shared KV buffer ----
        {
            const float* kp = isnew
                ? g_knew + ((long)(b * 16 + rel)) * 1024 + kvh * 128 + dh
                : mem_k + coff;
#pragma unroll
            for (int i = 0; i < 8; i++) {
                float4 v = *(const float4*)(kp + i * 4);
                float x[4] = {v.x, v.y, v.z, v.w};
#pragma unroll
                for (int u = 0; u < 4; u += 2) {
                    __nv_bfloat162 lo;
                    __nv_bfloat162 hi = split_hi2(x[u], x[u + 1], &lo);
                    int d = dh + i * 4 + u;
                    *(__nv_bfloat162*)&sKVh[jj * LDKV + d] = hi;
                    *(__nv_bfloat162*)&sKVl[jj * LDKV + d] = lo;
                }
            }
        }
        __syncthreads();

        // ---- QK^T: S[64 q][64 keys] ----
        float acc[2][2][4];
#pragma unroll
        for (int mi = 0; mi < 2; mi++)
#pragma unroll
            for (int ni = 0; ni < 2; ni++)
#pragma unroll
                for (int f = 0; f < 4; f++) acc[mi][ni][f] = 0.f;

#pragma unroll
        for (int kk = 0; kk < 128; kk += 16) {
            uint32_t ah[2][4], al[2][4];
#pragma unroll
            for (int mi = 0; mi < 2; mi++) {
                int r = warp_m + mi * 16 + (lane & 15);
                int c = kk + (lane >> 4) * 8;
                ldsm_x4(ah[mi], cvta_s(&sQh[r * LDQ + c]));
                ldsm_x4(al[mi], cvta_s(&sQl[r * LDQ + c]));
            }
            uint32_t bh[2][2], bl[2][2];
#pragma unroll
            for (int ni = 0; ni < 2; ni++) {
                int nrow = warp_nq + ni * 8 + (lane & 7);
                int kcol = kk + ((lane >> 3) & 1) * 8;
                ldsm_x2(bh[ni], cvta_s(&sKVh[nrow * LDKV + kcol]));
                ldsm_x2(bl[ni], cvta_s(&sKVl[nrow * LDKV + kcol]));
            }
#pragma unroll
            for (int mi = 0; mi < 2; mi++)
#pragma unroll
                for (int ni = 0; ni < 2; ni++) {
                    mma_bf16(acc[mi][ni], ah[mi], bh[ni]);
                    mma_bf16(acc[mi][ni], ah[mi], bl[ni]);
                    mma_bf16(acc[mi][ni], al[mi], bh[ni]);
                }
        }

        // ---- capped softmax numerator -> P, row sums -> sRow ----
#pragma unroll
        for (int mi = 0; mi < 2; mi++) {
            int r_lo = warp_m + mi * 16 + (lane >> 2);
            int r_hi = r_lo + 8;
            float s0 = 0.f, s1 = 0.f;
#pragma unroll
            for (int ni = 0; ni < 2; ni++) {
                int c0 = warp_nq + ni * 8 + (lane & 3) * 2;
                float p[4];
#pragma unroll
                for (int f = 0; f < 4; f++) {
                    int jg = jb + c0 + (f & 1);
                    float u = acc[mi][ni][f] * (MULT / 30.f);
                    float t2 = __expf(-2.f * fabsf(u));
                    float th = __fdividef(1.f - t2, 1.f + t2);
                    th = copysignf(th, u);
                    p[f] = (jg < nstep) ? __expf(30.f * th) : 0.f;
                }
                s0 += p[0] + p[1];
                s1 += p[2] + p[3];
                __nv_bfloat162 lo;
                __nv_bfloat162 hi = split_hi2(p[0], p[1], &lo);
                *(__nv_bfloat162*)&sPh[r_lo * LDP + c0] = hi;
                *(__nv_bfloat162*)&sPl[r_lo * LDP + c0] = lo;
                hi = split_hi2(p[2], p[3], &lo);
                *(__nv_bfloat162*)&sPh[r_hi * LDP + c0] = hi;
                *(__nv_bfloat162*)&sPl[r_hi * LDP + c0] = lo;
            }
            s0 += __shfl_xor_sync(0xffffffff, s0, 1);
            s0 += __shfl_xor_sync(0xffffffff, s0, 2);
            s1 += __shfl_xor_sync(0xffffffff, s1, 1);
            s1 += __shfl_xor_sync(0xffffffff, s1, 2);
            if ((lane & 3) == 0) {
                atomicAdd(&sRow[r_lo], s0);
                atomicAdd(&sRow[r_hi], s1);
            }
        }
        __syncthreads();    // QK done reading K; P written

        // ---- stage V over the K buffer ----
        {
            const float* vp = isnew
                ? g_pqkv + ((long)(b * 16 + rel)) * 6144 + 5120 + kvh * 128 + dh
                : mem_v + coff;
#pragma unroll
            for (int i = 0; i < 8; i++) {
                float4 v = *(const float4*)(vp + i * 4);
                float x[4] = {v.x, v.y, v.z, v.w};
#pragma unroll
                for (int u = 0; u < 4; u += 2) {
                    __nv_bfloat162 lo;
                    __nv_bfloat162 hi = split_hi2(x[u], x[u + 1], &lo);
                    int d = dh + i * 4 + u;
                    *(__nv_bfloat162*)&sKVh[jj * LDKV + d] = hi;
                    *(__nv_bfloat162*)&sKVl[jj * LDKV + d] = lo;
                }
            }
        }
        __syncthreads();

        // ---- PV accumulate: oacc += P[64x64] @ V[64x128] ----
#pragma unroll
        for (int kk = 0; kk < 64; kk += 16) {
            uint32_t ph[2][4], pl[2][4];
#pragma unroll
            for (int mi = 0; mi < 2; mi++) {
                int r = warp_m + mi * 16 + (lane & 15);
                int c = kk + (lane >> 4) * 8;
                ldsm_x4(ph[mi], cvta_s(&sPh[r * LDP + c]));
                ldsm_x4(pl[mi], cvta_s(&sPl[r * LDP + c]));
            }
            uint32_t vh[4][2], vl[4][2];
#pragma unroll
            for (int ni = 0; ni < 4; ni++) {
                int r = kk + (lane & 15);
                int c = warp_nv + ni * 8;
                ldsm_x2t(vh[ni], cvta_s(&sKVh[r * LDKV + c]));
                ldsm_x2t(vl[ni], cvta_s(&sKVl[r * LDKV + c]));
            }
#pragma unroll
            for (int mi = 0; mi < 2; mi++)
#pragma unroll
                for (int ni = 0; ni < 4; ni++) {
                    mma_bf16(oacc[mi][ni], ph[mi], vh[ni]);
                    mma_bf16(oacc[mi][ni], ph[mi], vl[ni]);
                    mma_bf16(oacc[mi][ni], pl[mi], vh[ni]);
                }
        }
    }
    __syncthreads();

    int pbase = (b * 8 + kvh) * 16 + blkc;
    if (tid < 64) g_pl[pbase * 64 + tid] = sRow[tid];

    float* dst = &g_pacc[(long)pbase * 8192];
#pragma unroll
    for (int mi = 0; mi < 2; mi++) {
        int r_lo = warp_m + mi * 16 + (lane >> 2);
#pragma unroll
        for (int ni = 0; ni < 4; ni++) {
            int d0 = warp_nv + ni * 8 + (lane & 3) * 2;
            *(float2*)&dst[r_lo * 128 + d0] = make_float2(oacc[mi][ni][0], oacc[mi][ni][1]);
            *(float2*)&dst[(r_lo + 8) * 128 + d0] = make_float2(oacc[mi][ni][2], oacc[mi][ni][3]);
        }
    }
}

// ---------------- Combine partials -> split bf16 A for O-proj ----------------
__global__ void combine_kernel(const int* __restrict__ step) {
    int blk = blockIdx.x;
    int qi = blk & 63;
    int bk = blk >> 6;
    int kvh = bk & 7, b = bk >> 3;
    int d = threadIdx.x;           // 128
    int nstep = step[b] + TT;
    int nch = (nstep + 255) >> 8;
    if (nch > 16) nch = 16;
    float asum = 0.f, lsum = 0.f;
    int base = bk * 16;
    for (int c = 0; c < nch; c++)
        asum += g_pacc[(long)(base + c) * 8192 + qi * 128 + d];
    for (int c = 0; c < nch; c++)
        lsum += g_pl[(base + c) * 64 + qi];
    int t = qi & 15, hg = qi >> 4;
    float val = asum / lsum;
    long oidx = (((long)(b * 16 + t)) * 32 + kvh * 4 + hg) * 128 + d;
    __nv_bfloat16 h = __float2bfloat16(val);
    g_ah[oidx] = h;
    g_al[oidx] = __float2bfloat16(val - __bfloat162float(h));
}

// ---------------- launch ------------------------------------------------------
extern "C" void kernel_launch(void* const* d_in, const int* in_sizes, int n_in,
                              void* d_out, int out_size)
{
    const float*   query = (const float*)d_in[0];
    const float*   keyx  = (const float*)d_in[1];
    const float*   value = (const float*)d_in[2];
    const float*   mem_k = (const float*)d_in[4];
    const float*   mem_v = (const float*)d_in[5];
    const int*     step  = (const int*)d_in[6];
    const void*    wq = d_in[7];
    const float*   sq = (const float*)d_in[8];
    const void*    wk = d_in[9];
    const float*   sk = (const float*)d_in[10];
    const void*    wv = d_in[11];
    const float*   sv = (const float*)d_in[12];
    const void*    wo = d_in[13];
    const float*   so = (const float*)d_in[14];

    float* out = (float*)d_out;
    float* kc    = out + OFF_KC;
    float* vc    = out + OFF_VC;
    float* ostep = out + OFF_STEP;

    // Side stream (created once) for the independent full cache copy.
    static cudaStream_t s1 = nullptr;
    static cudaEvent_t ev0 = nullptr, ev1 = nullptr;
    static bool sok = false;
    if (!s1) {
        sok = (cudaStreamCreateWithFlags(&s1, cudaStreamNonBlocking) == cudaSuccess) &&
              (cudaEventCreateWithFlags(&ev0, cudaEventDisableTiming) == cudaSuccess) &&
              (cudaEventCreateWithFlags(&ev1, cudaEventDisableTiming) == cudaSuccess);
    }

    if (sok) {
        cudaEventRecord(ev0, 0);
        cudaStreamWaitEvent(s1, ev0, 0);
        copy_cache<<<512, 256, 0, s1>>>((const uint4*)mem_k, (uint4*)kc,
                                        (const uint4*)mem_v, (uint4*)vc);
        cudaEventRecord(ev1, s1);
    } else {
        copy_cache<<<512, 256>>>((const uint4*)mem_k, (uint4*)kc,
                                 (const uint4*)mem_v, (uint4*)vc);
    }

    detect_wdtype<<<1, 256>>>(wq);

    float *pqkv, *part;
    __nv_bfloat16 *ah, *al;
    cudaGetSymbolAddress((void**)&pqkv, g_pqkv);
    cudaGetSymbolAddress((void**)&part, g_part);
    cudaGetSymbolAddress((void**)&ah, g_ah);
    cudaGetSymbolAddress((void**)&al, g_al);

    cudaFuncSetAttribute(gemm_tc, cudaFuncAttributeMaxDynamicSharedMemorySize, GEMM_SMEM);
    cudaFuncSetAttribute(attn_tc, cudaFuncAttributeMaxDynamicSharedMemorySize, ATTN_SMEM);

    // Fused QKV projection
    presplit_all<<<1536, 1024>>>(query, keyx, value);
    gemm_tc<<<dim3(96, 8), 256, GEMM_SMEM>>>(ah, al, wq, sq, wk, sk, wv, sv,
                                             part, 0, 512);
    reduce_splitk<<<768, 256>>>(part, pqkv, 196608, 8);

    // RoPE + new_step
    rope_fused<<<1280, 256>>>(step, ostep);

    // Tensor-core attention: 4x64-key chunks per block, 2 blocks/SM
    attn_tc<<<dim3(16, 8, 8), 256, ATTN_SMEM>>>(mem_k, mem_v, step);
    combine_kernel<<<4096, 128>>>(step);

    // Output projection (16-way split-K)
    gemm_tc<<<dim3(64, 16), 256, GEMM_SMEM>>>(ah, al, wo, so, wo, so, wo, so,
                                              part, 1, 256);
    reduce_splitk<<<512, 256>>>(part, out, 131072, 16);

    // Join copy stream, then scatter the 16 new rows into kc/vc
    if (sok) cudaStreamWaitEvent(0, ev1, 0);
    scatter_new<<<512, 256>>>(step, kc, vc);
}

// round 17
// speedup vs baseline: 1.1610x; 1.0349x over previous
#include <cuda_runtime.h>
#include <cuda_bf16.h>
#include <cstdint>
#include <cmath>

// Problem constants
#define BB 8
#define TT 16
#define DD 4096
#define MM 4096
#define HQ 32
#define HK 8
#define DKH 128
#define NROWS 128      // B*T
#define MULT 0.08838834764831845f

// Output layout (fp32 elements): out | kc | vc | new_step
#define OFF_KC   (524288)
#define OFF_VC   (OFF_KC + 33554432)
#define OFF_STEP (OFF_VC + 33554432)

// ---------------- scratch (device globals; no allocation allowed) -------------
__device__ float g_pqkv[NROWS * 6144];      // fused qkv proj (q|k|v cols)
__device__ float g_knew[NROWS * 1024];      // rope'd k (new rows)
__device__ __align__(16) __nv_bfloat16 g_qh[8 * 8 * 64 * 128];  // rope'd q hi
__device__ __align__(16) __nv_bfloat16 g_ql[8 * 8 * 64 * 128];  // rope'd q lo
__device__ __align__(16) __nv_bfloat16 g_ah[3 * NROWS * 4096];  // pre-split A hi (q|k|v)
__device__ __align__(16) __nv_bfloat16 g_al[3 * NROWS * 4096];  // pre-split A lo
__device__ float g_pacc[1024L * 64 * 128];  // partial PV accumulators (33.5MB)
__device__ float g_pl[1024 * 64];           // partial softmax denominators
__device__ int   g_wflag;                   // 0=int8 packed, 1=int32, 2=float32

// ---------------- weight dtype detection -------------------------------------
__global__ void detect_wdtype(const void* __restrict__ w) {
    int tid = threadIdx.x;
    const int* wi = (const int*)w;
    int v = wi[tid];
    bool small = (v >= -127 && v <= 127);
    int all_small = __syncthreads_and((int)small);
    if (all_small) { if (tid == 0) g_wflag = 1; return; }
    float fv = __int_as_float(v);
    bool isf = isfinite(fv) && fabsf(fv) <= 127.0f && fv == rintf(fv);
    int all_f = __syncthreads_and((int)isf);
    if (tid == 0) g_wflag = all_f ? 2 : 0;
}

// ---------------- SM-path cache copy (side stream) ---------------------------
__global__ void copy_cache(const uint4* __restrict__ src_k, uint4* __restrict__ dst_k,
                           const uint4* __restrict__ src_v, uint4* __restrict__ dst_v)
{
    const long n4 = 8388608;   // 33554432 floats / 4
    long stride = (long)gridDim.x * blockDim.x;
    for (long i = (long)blockIdx.x * blockDim.x + threadIdx.x; i < n4; i += stride) {
        dst_k[i] = src_k[i];
        dst_v[i] = src_v[i];
    }
}

// ---------------- tensor-core / async helpers ---------------------------------
__device__ __forceinline__ uint32_t cvta_s(const void* p) {
    return (uint32_t)__cvta_generic_to_shared(p);
}
__device__ __forceinline__ void ldsm_x4(uint32_t* r, uint32_t a) {
    asm volatile("ldmatrix.sync.aligned.m8n8.x4.shared.b16 {%0,%1,%2,%3}, [%4];"
        : "=r"(r[0]), "=r"(r[1]), "=r"(r[2]), "=r"(r[3]) : "r"(a));
}
__device__ __forceinline__ void ldsm_x2t(uint32_t* r, uint32_t a) {
    asm volatile("ldmatrix.sync.aligned.m8n8.x2.trans.shared.b16 {%0,%1}, [%2];"
        : "=r"(r[0]), "=r"(r[1]) : "r"(a));
}
__device__ __forceinline__ void ldsm_x2(uint32_t* r, uint32_t a) {
    asm volatile("ldmatrix.sync.aligned.m8n8.x2.shared.b16 {%0,%1}, [%2];"
        : "=r"(r[0]), "=r"(r[1]) : "r"(a));
}
__device__ __forceinline__ void mma_bf16(float* c, const uint32_t* a, const uint32_t* b) {
    asm volatile("mma.sync.aligned.m16n8k16.row.col.f32.bf16.bf16.f32 "
        "{%0,%1,%2,%3}, {%4,%5,%6,%7}, {%8,%9}, {%0,%1,%2,%3};"
        : "+f"(c[0]), "+f"(c[1]), "+f"(c[2]), "+f"(c[3])
        : "r"(a[0]), "r"(a[1]), "r"(a[2]), "r"(a[3]), "r"(b[0]), "r"(b[1]));
}
__device__ __forceinline__ void cp16(uint32_t dst, const void* src) {
    asm volatile("cp.async.cg.shared.global [%0], [%1], 16;" :: "r"(dst), "l"(src));
}
__device__ __forceinline__ void cp_commit() {
    asm volatile("cp.async.commit_group;");
}
__device__ __forceinline__ void cp_wait0() {
    asm volatile("cp.async.wait_group 0;");
}
__device__ __forceinline__ __nv_bfloat162 split_hi2(float a, float b, __nv_bfloat162* lo) {
    __nv_bfloat16 h0 = __float2bfloat16(a);
    __nv_bfloat16 h1 = __float2bfloat16(b);
    *lo = __halves2bfloat162(__float2bfloat16(a - __bfloat162float(h0)),
                             __float2bfloat16(b - __bfloat162float(h1)));
    return __halves2bfloat162(h0, h1);
}

// ---------------- A pre-split (q|k|v fused) -----------------------------------
__global__ void presplit_all(const float* __restrict__ q,
                             const float* __restrict__ k,
                             const float* __restrict__ v) {
    int idx = blockIdx.x * blockDim.x + threadIdx.x;   // 3*524288
    int sel = idx >> 19;
    int off = idx & 524287;
    const float* src = (sel == 0) ? q : (sel == 1) ? k : v;
    float a = src[off];
    __nv_bfloat16 h = __float2bfloat16(a);
    g_ah[idx] = h;
    g_al[idx] = __float2bfloat16(a - __bfloat162float(h));
}

// ---------------- pipelined split-bf16 tensor-core GEMM (RED epilogue) --------
// mode 0: fused QKV (Nout=6144), mode 1: single (Nout=4096)
// Split-K partials are atomically accumulated into the (L2-resident) target.
#define LDA 40
#define LDW 72
#define GEMM_SMEM ((4 * 128 * LDA + 4 * 32 * LDW) * 2)
__global__ __launch_bounds__(256, 3) void gemm_tc(
    const __nv_bfloat16* __restrict__ AhBase, const __nv_bfloat16* __restrict__ AlBase,
    const void* __restrict__ W0, const float* __restrict__ S0,
    const void* __restrict__ W1, const float* __restrict__ S1,
    const void* __restrict__ W2, const float* __restrict__ S2,
    float* __restrict__ C, int mode, int kchunk)
{
    extern __shared__ __nv_bfloat16 smg[];
    __nv_bfloat16* sA_h = smg;                     // [2][128*LDA]
    __nv_bfloat16* sA_l = smg + 2 * 128 * LDA;
    __nv_bfloat16* sW_h = smg + 4 * 128 * LDA;     // [2][32*LDW]
    __nv_bfloat16* sW_l = smg + 4 * 128 * LDA + 2 * 32 * LDW;

    const int K = 4096;
    int bn = blockIdx.x * 64;
    int ks = blockIdx.y;
    int kbeg = ks * kchunk;
    int tid = threadIdx.x;
    int wid = tid >> 5, lane = tid & 31;
    int wf = g_wflag;

    const void* W; const float* S; int Nw, bnl, Nout, asel;
    if (mode == 0) {
        Nout = 6144;
        if (bn < 4096)      { W = W0; S = S0; Nw = 4096; bnl = bn;        asel = 0; }
        else if (bn < 5120) { W = W1; S = S1; Nw = 1024; bnl = bn - 4096; asel = 1; }
        else                { W = W2; S = S2; Nw = 1024; bnl = bn - 5120; asel = 2; }
    } else { W = W0; S = S0; Nw = 4096; bnl = bn; Nout = 4096; asel = 0; }
    const __nv_bfloat16* Ah = AhBase + (long)asel * 524288;
    const __nv_bfloat16* Al = AlBase + (long)asel * 524288;

    int warp_m = (wid >> 1) * 32;
    int warp_n = (wid & 1) * 32;

    float acc[2][4][4];
#pragma unroll
    for (int mi = 0; mi < 2; mi++)
#pragma unroll
        for (int ni = 0; ni < 4; ni++)
#pragma unroll
            for (int f = 0; f < 4; f++) acc[mi][ni][f] = 0.f;

    int arow = tid >> 1, aseg = (tid & 1) * 16;
    int wrow = tid >> 3, wnoff = (tid & 7) * 8;

    uint4 rwa = {0,0,0,0}, rwb = {0,0,0,0};
    float4 rs0, rs1;

    auto cpA = [&](int kt, int buf) {
        long go = (long)arow * K + kt + aseg;
        uint32_t dh = cvta_s(sA_h + buf * 128 * LDA + arow * LDA + aseg);
        uint32_t dl = cvta_s(sA_l + buf * 128 * LDA + arow * LDA + aseg);
        cp16(dh, Ah + go);      cp16(dh + 16, Ah + go + 8);
        cp16(dl, Al + go);      cp16(dl + 16, Al + go + 8);
    };
    auto loadW = [&](int kt) {
        long wo = (long)(kt + wrow) * Nw + bnl + wnoff;
        if (wf == 1) {
            rwa = *(const uint4*)((const int*)W + wo);
            rwb = *(const uint4*)((const int*)W + wo + 4);
        } else if (wf == 0) {
            uint2 r8 = *(const uint2*)((const int8_t*)W + wo);
            rwa.x = r8.x; rwa.y = r8.y;
        } else {
            rwa = *(const uint4*)((const float*)W + wo);
            rwb = *(const uint4*)((const float*)W + wo + 4);
        }
        rs0 = *(const float4*)(S + wo);
        rs1 = *(const float4*)(S + wo + 4);
    };
    auto storeW = [&](int buf) {
        float wd[8];
        if (wf == 1) {
            wd[0] = (float)(int)rwa.x; wd[1] = (float)(int)rwa.y;
            wd[2] = (float)(int)rwa.z; wd[3] = (float)(int)rwa.w;
            wd[4] = (float)(int)rwb.x; wd[5] = (float)(int)rwb.y;
            wd[6] = (float)(int)rwb.z; wd[7] = (float)(int)rwb.w;
        } else if (wf == 0) {
#pragma unroll
            for (int i = 0; i < 4; i++) wd[i]     = (float)(int)(char)(rwa.x >> (8 * i));
#pragma unroll
            for (int i = 0; i < 4; i++) wd[4 + i] = (float)(int)(char)(rwa.y >> (8 * i));
        } else {
            wd[0] = __uint_as_float(rwa.x); wd[1] = __uint_as_float(rwa.y);
            wd[2] = __uint_as_float(rwa.z); wd[3] = __uint_as_float(rwa.w);
            wd[4] = __uint_as_float(rwb.x); wd[5] = __uint_as_float(rwb.y);
            wd[6] = __uint_as_float(rwb.z); wd[7] = __uint_as_float(rwb.w);
        }
        float sc[8] = {rs0.x, rs0.y, rs0.z, rs0.w, rs1.x, rs1.y, rs1.z, rs1.w};
        __nv_bfloat16* bh = sW_h + buf * 32 * LDW + wrow * LDW + wnoff;
        __nv_bfloat16* bl = sW_l + buf * 32 * LDW + wrow * LDW + wnoff;
#pragma unroll
        for (int j = 0; j < 8; j += 2) {
            __nv_bfloat162 lo;
            __nv_bfloat162 hi = split_hi2(wd[j] * sc[j], wd[j + 1] * sc[j + 1], &lo);
            *(__nv_bfloat162*)&bh[j] = hi;
            *(__nv_bfloat162*)&bl[j] = lo;
        }
    };

    int nb = kchunk / 32;
    cpA(kbeg, 0); cp_commit();
    loadW(kbeg);

    for (int it = 0; it < nb; it++) {
        int cur = it & 1;
        storeW(cur);
        cp_wait0();
        __syncthreads();
        if (it + 1 < nb) {
            cpA(kbeg + (it + 1) * 32, cur ^ 1); cp_commit();
            loadW(kbeg + (it + 1) * 32);
        }
        const __nv_bfloat16* aH = sA_h + cur * 128 * LDA;
        const __nv_bfloat16* aL = sA_l + cur * 128 * LDA;
        const __nv_bfloat16* wH = sW_h + cur * 32 * LDW;
        const __nv_bfloat16* wL = sW_l + cur * 32 * LDW;
#pragma unroll
        for (int kk = 0; kk < 32; kk += 16) {
            uint32_t ah[2][4], al[2][4];
#pragma unroll
            for (int mi = 0; mi < 2; mi++) {
                int r = warp_m + mi * 16 + (lane & 15);
                int c = kk + (lane >> 4) * 8;
                ldsm_x4(ah[mi], cvta_s(&aH[r * LDA + c]));
                ldsm_x4(al[mi], cvta_s(&aL[r * LDA + c]));
            }
            uint32_t bh[4][2], bl[4][2];
#pragma unroll
            for (int ni = 0; ni < 4; ni++) {
                int r = kk + (lane & 15);
                int c = warp_n + ni * 8;
                ldsm_x2t(bh[ni], cvta_s(&wH[r * LDW + c]));
                ldsm_x2t(bl[ni], cvta_s(&wL[r * LDW + c]));
            }
#pragma unroll
            for (int mi = 0; mi < 2; mi++)
#pragma unroll
                for (int ni = 0; ni < 4; ni++) {
                    mma_bf16(acc[mi][ni], ah[mi], bh[ni]);
                    mma_bf16(acc[mi][ni], ah[mi], bl[ni]);
                    mma_bf16(acc[mi][ni], al[mi], bh[ni]);
                }
        }
    }

    // ---- RED epilogue: atomically accumulate into (L2-resident) C ----
    int r0 = lane >> 2, c0 = (lane & 3) * 2;
#pragma unroll
    for (int mi = 0; mi < 2; mi++)
#pragma unroll
        for (int ni = 0; ni < 4; ni++) {
            float* cp = C + (long)(warp_m + mi * 16 + r0) * Nout + bn + warp_n + ni * 8 + c0;
            atomicAdd(cp, acc[mi][ni][0]);
            atomicAdd(cp + 1, acc[mi][ni][1]);
            float* cp2 = cp + 8 * (long)Nout;
            atomicAdd(cp2, acc[mi][ni][2]);
            atomicAdd(cp2 + 1, acc[mi][ni][3]);
        }
}

// ---------------- fused RoPE (q -> g_qh/g_ql split, k -> g_knew) + step ------
__global__ void rope_fused(const int* __restrict__ step, float* __restrict__ ostep) {
    int idx = blockIdx.x * blockDim.x + threadIdx.x;  // 262144 + 65536
    if (blockIdx.x == 0 && threadIdx.x < BB)
        ostep[threadIdx.x] = (float)(step[threadIdx.x] + TT);
    if (idx < 262144) {
        int row = idx >> 11;
        int rem = idx & 2047;
        int h = rem >> 6, j = rem & 63;
        int b = row >> 4, t = row & 15;
        float x1 = g_pqkv[(long)row * 6144 + h * 128 + j];
        float x2 = g_pqkv[(long)row * 6144 + h * 128 + j + 64];
        float pos = (float)(t + step[b]);
        float invf = (float)exp(-(double)j * 0.14391156831212787);
        float ph = pos * invf;
        float c = cosf(ph), s = sinf(ph);
        float y1 = x1 * c - x2 * s;
        float y2 = x2 * c + x1 * s;
        int kvh = h >> 2, hg = h & 3;
        long orow = ((long)(b * 8 + kvh)) * 64 + hg * 16 + t;
        __nv_bfloat16 h1 = __float2bfloat16(y1);
        __nv_bfloat16 h2 = __float2bfloat16(y2);
        g_qh[orow * 128 + j]      = h1;
        g_ql[orow * 128 + j]      = __float2bfloat16(y1 - __bfloat162float(h1));
        g_qh[orow * 128 + j + 64] = h2;
        g_ql[orow * 128 + j + 64] = __float2bfloat16(y2 - __bfloat162float(h2));
    } else {
        int i2 = idx - 262144;     // 65536 k elems
        int row = i2 >> 9;
        int rem = i2 & 511;
        int h = rem >> 6, j = rem & 63;
        int b = row >> 4, t = row & 15;
        float x1 = g_pqkv[(long)row * 6144 + 4096 + h * 128 + j];
        float x2 = g_pqkv[(long)row * 6144 + 4096 + h * 128 + j + 64];
        int pos = t + step[b];
        float invf = (float)exp(-(double)j * 0.14391156831212787);
        float ph = (float)pos * invf;
        float c = cosf(ph), s = sinf(ph);
        float* dst = g_knew + (long)row * 1024 + h * 128;
        dst[j]      = x1 * c - x2 * s;
        dst[j + 64] = x2 * c + x1 * s;
    }
}

// ---------------- final scatter of new rows into kc/vc ------------------------
__global__ void scatter_new(const int* __restrict__ step,
                            float* __restrict__ kc, float* __restrict__ vc) {
    int idx = blockIdx.x * blockDim.x + threadIdx.x;   // 128*1024
    int row = idx >> 10;
    int rem = idx & 1023;
    int b = row >> 4, t = row & 15;
    int h = rem >> 7, d = rem & 127;
    long gi = (((long)b * MM + (step[b] + t)) * HK + h) * DKH + d;
    kc[gi] = g_knew[idx];
    vc[gi] = g_pqkv[(long)row * 6144 + 5120 + rem];
}

// ---------------- Tensor-core attention: 4x64-key chunks per block -----------
// Register-accumulated PV across chunks; K/V share one smem buffer.
#define LDQ 136
#define LDKV 136
#define LDP 72
#define ATTN_SMEM ((2*64*LDQ + 2*64*LDKV + 2*64*LDP) * 2 + 256)
__global__ __launch_bounds__(256, 2) void attn_tc(
    const float* __restrict__ mem_k, const float* __restrict__ mem_v,
    const int* __restrict__ step)
{
    extern __shared__ char smraw[];
    __nv_bfloat16* sQh = (__nv_bfloat16*)smraw;            // 64 x LDQ
    __nv_bfloat16* sQl = sQh + 64 * LDQ;
    __nv_bfloat16* sKVh = sQl + 64 * LDQ;                  // 64 x LDKV (K then V)
    __nv_bfloat16* sKVl = sKVh + 64 * LDKV;
    __nv_bfloat16* sPh = sKVl + 64 * LDKV;                 // 64 x LDP
    __nv_bfloat16* sPl = sPh + 64 * LDP;
    float* sRow = (float*)(sPl + 64 * LDP);

    int blkc = blockIdx.x, kvh = blockIdx.y, b = blockIdx.z;
    int tid = threadIdx.x;
    int wid = tid >> 5, lane = tid & 31;
    int j0 = blkc * 256;
    int stepb = step[b];
    int nstep = stepb + TT;
    if (j0 >= nstep) return;

    if (tid < 64) sRow[tid] = 0.f;

    // ---- stage Q (once, reused for 4 chunks) ----
    {
        const uint4* qh = (const uint4*)(g_qh + ((long)(b * 8 + kvh)) * 64 * 128);
        const uint4* ql = (const uint4*)(g_ql + ((long)(b * 8 + kvh)) * 64 * 128);
        for (int i = tid; i < 1024; i += 256) {
            int qi = i >> 4, seg = (i & 15) * 8;
            *(uint4*)&sQh[qi * LDQ + seg] = qh[i];
            *(uint4*)&sQl[qi * LDQ + seg] = ql[i];
        }
    }

    int warp_m = (wid >> 2) * 32;
    int warp_nq = (wid & 3) * 16;
    int warp_nv = (wid & 3) * 32;

    int jj = tid >> 2, dh = (tid & 3) * 32;   // staging coords (64 rows x 128 d)

    float oacc[2][4][4];
#pragma unroll
    for (int mi = 0; mi < 2; mi++)
#pragma unroll
        for (int ni = 0; ni < 4; ni++)
#pragma unroll
            for (int f = 0; f < 4; f++) oacc[mi][ni][f] = 0.f;

    for (int c4 = 0; c4 < 4; c4++) {
        int jb = j0 + c4 * 64;
        if (jb >= nstep) break;

        int pos = jb + jj;
        int rel = pos - stepb;
        bool isnew = (rel >= 0 && rel < TT);
        long coff = (((long)b * MM + pos) * HK + kvh) * DKH + dh;

        __syncthreads();    // prev PV done reading KV; Q staged (iter 0)

        // ---- stage K into shared KV buffer ----
        {
            const float* kp = isnew
                ? g_knew + ((long)(b * 16 + rel)) * 1024 + kvh * 128 + dh
                : mem_k + coff;
#pragma unroll
            for (int i = 0; i < 8; i++) {
                float4 v = *(const float4*)(kp + i * 4);
                float x[4] = {v.x, v.y, v.z, v.w};
#pragma unroll
                for (int u = 0; u < 4; u += 2) {
                    __nv_bfloat162 lo;
                    __nv_bfloat162 hi = split_hi2(x[u], x[u + 1], &lo);
                    int d = dh + i * 4 + u;
                    *(__nv_bfloat162*)&sKVh[jj * LDKV + d] = hi;
                    *(__nv_bfloat162*)&sKVl[jj * LDKV + d] = lo;
                }
            }
        }
        __syncthreads();

        // ---- QK^T: S[64 q][64 keys] ----
        float acc[2][2][4];
#pragma unroll
        for (int mi = 0; mi < 2; mi++)
#pragma unroll
            for (int ni = 0; ni < 2; ni++)
#pragma unroll
                for (int f = 0; f < 4; f++) acc[mi][ni][f] = 0.f;

#pragma unroll
        for (int kk = 0; kk < 128; kk += 16) {
            uint32_t ah[2][4], al[2][4];
#pragma unroll
            for (int mi = 0; mi < 2; mi++) {
                int r = warp_m + mi * 16 + (lane & 15);
                int c = kk + (lane >> 4) * 8;
                ldsm_x4(ah[mi], cvta_s(&sQh[r * LDQ + c]));
                ldsm_x4(al[mi], cvta_s(&sQl[r * LDQ + c]));
            }
            uint32_t bh[2][2], bl[2][2];
#pragma unroll
            for (int ni = 0; ni < 2; ni++) {
                int nrow = warp_nq + ni * 8 + (lane & 7);
                int kcol = kk + ((lane >> 3) & 1) * 8;
                ldsm_x2(bh[ni], cvta_s(&sKVh[nrow * LDKV + kcol]));
                ldsm_x2(bl[ni], cvta_s(&sKVl[nrow * LDKV + kcol]));
            }
#pragma unroll
            for (int mi = 0; mi < 2; mi++)
#pragma unroll
                for (int ni = 0; ni < 2; ni++) {
                    mma_bf16(acc[mi][ni], ah[mi], bh[ni]);
                    mma_bf16(acc[mi][ni], ah[mi], bl[ni]);
                    mma_bf16(acc[mi][ni], al[mi], bh[ni]);
                }
        }

        // ---- capped softmax numerator -> P, row sums -> sRow ----
#pragma unroll
        for (int mi = 0; mi < 2; mi++) {
            int r_lo = warp_m + mi * 16 + (lane >> 2);
            int r_hi = r_lo + 8;
            float s0 = 0.f, s1 = 0.f;
#pragma unroll
            for (int ni = 0; ni < 2; ni++) {
                int c0 = warp_nq + ni * 8 + (lane & 3) * 2;
                float p[4];
#pragma unroll
                for (int f = 0; f < 4; f++) {
                    int jg = jb + c0 + (f & 1);
                    float u = acc[mi][ni][f] * (MULT / 30.f);
                    float t2 = __expf(-2.f * fabsf(u));
                    float th = __fdividef(1.f - t2, 1.f + t2);
                    th = copysignf(th, u);
                    p[f] = (jg < nstep) ? __expf(30.f * th) : 0.f;
                }
                s0 += p[0] + p[1];
                s1 += p[2] + p[3];
                __nv_bfloat162 lo;
                __nv_bfloat162 hi = split_hi2(p[0], p[1], &lo);
                *(__nv_bfloat162*)&sPh[r_lo * LDP + c0] = hi;
                *(__nv_bfloat162*)&sPl[r_lo * LDP + c0] = lo;
                hi = split_hi2(p[2], p[3], &lo);
                *(__nv_bfloat162*)&sPh[r_hi * LDP + c0] = hi;
                *(__nv_bfloat162*)&sPl[r_hi * LDP + c0] = lo;
            }
            s0 += __shfl_xor_sync(0xffffffff, s0, 1);
            s0 += __shfl_xor_sync(0xffffffff, s0, 2);
            s1 += __shfl_xor_sync(0xffffffff, s1, 1);
            s1 += __shfl_xor_sync(0xffffffff, s1, 2);
            if ((lane & 3) == 0) {
                atomicAdd(&sRow[r_lo], s0);
                atomicAdd(&sRow[r_hi], s1);
            }
        }
        __syncthreads();    // QK done reading K; P written

        // ---- stage V over the K buffer ----
        {
            const float* vp = isnew
                ? g_pqkv + ((long)(b * 16 + rel)) * 6144 + 5120 + kvh * 128 + dh
                : mem_v + coff;
#pragma unroll
            for (int i = 0; i < 8; i++) {
                float4 v = *(const float4*)(vp + i * 4);
                float x[4] = {v.x, v.y, v.z, v.w};
#pragma unroll
                for (int u = 0; u < 4; u += 2) {
                    __nv_bfloat162 lo;
                    __nv_bfloat162 hi = split_hi2(x[u], x[u + 1], &lo);
                    int d = dh + i * 4 + u;
                    *(__nv_bfloat162*)&sKVh[jj * LDKV + d] = hi;
                    *(__nv_bfloat162*)&sKVl[jj * LDKV + d] = lo;
                }
            }
        }
        __syncthreads();

        // ---- PV accumulate: oacc += P[64x64] @ V[64x128] ----
#pragma unroll
        for (int kk = 0; kk < 64; kk += 16) {
            uint32_t ph[2][4], pl[2][4];
#pragma unroll
            for (int mi = 0; mi < 2; mi++) {
                int r = warp_m + mi * 16 + (lane & 15);
                int c = kk + (lane >> 4) * 8;
                ldsm_x4(ph[mi], cvta_s(&sPh[r * LDP + c]));
                ldsm_x4(pl[mi], cvta_s(&sPl[r * LDP + c]));
            }
            uint32_t vh[4][2], vl[4][2];
#pragma unroll
            for (int ni = 0; ni < 4; ni++) {
                int r = kk + (lane & 15);
                int c = warp_nv + ni * 8;
                ldsm_x2t(vh[ni], cvta_s(&sKVh[r * LDKV + c]));
                ldsm_x2t(vl[ni], cvta_s(&sKVl[r * LDKV + c]));
            }
#pragma unroll
            for (int mi = 0; mi < 2; mi++)
#pragma unroll
                for (int ni = 0; ni < 4; ni++) {
                    mma_bf16(oacc[mi][ni], ph[mi], vh[ni]);
                    mma_bf16(oacc[mi][ni], ph[mi], vl[ni]);
                    mma_bf16(oacc[mi][ni], pl[mi], vh[ni]);
                }
        }
    }
    __syncthreads();

    int pbase = (b * 8 + kvh) * 16 + blkc;
    if (tid < 64) g_pl[pbase * 64 + tid] = sRow[tid];

    float* dst = &g_pacc[(long)pbase * 8192];
#pragma unroll
    for (int mi = 0; mi < 2; mi++) {
        int r_lo = warp_m + mi * 16 + (lane >> 2);
#pragma unroll
        for (int ni = 0; ni < 4; ni++) {
            int d0 = warp_nv + ni * 8 + (lane & 3) * 2;
            *(float2*)&dst[r_lo * 128 + d0] = make_float2(oacc[mi][ni][0], oacc[mi][ni][1]);
            *(float2*)&dst[(r_lo + 8) * 128 + d0] = make_float2(oacc[mi][ni][2], oacc[mi][ni][3]);
        }
    }
}

// ---------------- Combine partials -> split bf16 A for O-proj ----------------
__global__ void combine_kernel(const int* __restrict__ step) {
    int blk = blockIdx.x;
    int qi = blk & 63;
    int bk = blk >> 6;
    int kvh = bk & 7, b = bk >> 3;
    int d = threadIdx.x;           // 128
    int nstep = step[b] + TT;
    int nch = (nstep + 255) >> 8;
    if (nch > 16) nch = 16;
    float asum = 0.f, lsum = 0.f;
    int base = bk * 16;
    for (int c = 0; c < nch; c++)
        asum += g_pacc[(long)(base + c) * 8192 + qi * 128 + d];
    for (int c = 0; c < nch; c++)
        lsum += g_pl[(base + c) * 64 + qi];
    int t = qi & 15, hg = qi >> 4;
    float val = asum / lsum;
    long oidx = (((long)(b * 16 + t)) * 32 + kvh * 4 + hg) * 128 + d;
    __nv_bfloat16 h = __float2bfloat16(val);
    g_ah[oidx] = h;
    g_al[oidx] = __float2bfloat16(val - __bfloat162float(h));
}

// ---------------- launch ------------------------------------------------------
extern "C" void kernel_launch(void* const* d_in, const int* in_sizes, int n_in,
                              void* d_out, int out_size)
{
    const float*   query = (const float*)d_in[0];
    const float*   keyx  = (const float*)d_in[1];
    const float*   value = (const float*)d_in[2];
    const float*   mem_k = (const float*)d_in[4];
    const float*   mem_v = (const float*)d_in[5];
    const int*     step  = (const int*)d_in[6];
    const void*    wq = d_in[7];
    const float*   sq = (const float*)d_in[8];
    const void*    wk = d_in[9];
    const float*   sk = (const float*)d_in[10];
    const void*    wv = d_in[11];
    const float*   sv = (const float*)d_in[12];
    const void*    wo = d_in[13];
    const float*   so = (const float*)d_in[14];

    float* out = (float*)d_out;
    float* kc    = out + OFF_KC;
    float* vc    = out + OFF_VC;
    float* ostep = out + OFF_STEP;

    // Side stream (created once) for the independent full cache copy.
    static cudaStream_t s1 = nullptr;
    static cudaEvent_t ev0 = nullptr, ev1 = nullptr;
    static bool sok = false;
    if (!s1) {
        sok = (cudaStreamCreateWithFlags(&s1, cudaStreamNonBlocking) == cudaSuccess) &&
              (cudaEventCreateWithFlags(&ev0, cudaEventDisableTiming) == cudaSuccess) &&
              (cudaEventCreateWithFlags(&ev1, cudaEventDisableTiming) == cudaSuccess);
    }

    if (sok) {
        cudaEventRecord(ev0, 0);
        cudaStreamWaitEvent(s1, ev0, 0);
        copy_cache<<<512, 256, 0, s1>>>((const uint4*)mem_k, (uint4*)kc,
                                        (const uint4*)mem_v, (uint4*)vc);
        cudaEventRecord(ev1, s1);
    } else {
        copy_cache<<<512, 256>>>((const uint4*)mem_k, (uint4*)kc,
                                 (const uint4*)mem_v, (uint4*)vc);
    }

    detect_wdtype<<<1, 256>>>(wq);

    float *pqkv;
    __nv_bfloat16 *ah, *al;
    cudaGetSymbolAddress((void**)&pqkv, g_pqkv);
    cudaGetSymbolAddress((void**)&ah, g_ah);
    cudaGetSymbolAddress((void**)&al, g_al);

    cudaFuncSetAttribute(gemm_tc, cudaFuncAttributeMaxDynamicSharedMemorySize, GEMM_SMEM);
    cudaFuncSetAttribute(attn_tc, cudaFuncAttributeMaxDynamicSharedMemorySize, ATTN_SMEM);

    // Fused QKV projection: RED epilogue into zeroed L2-resident g_pqkv
    cudaMemsetAsync(pqkv, 0, (size_t)NROWS * 6144 * 4, 0);
    presplit_all<<<1536, 1024>>>(query, keyx, value);
    gemm_tc<<<dim3(96, 8), 256, GEMM_SMEM>>>(ah, al, wq, sq, wk, sk, wv, sv,
                                             pqkv, 0, 512);

    // RoPE + new_step
    rope_fused<<<1280, 256>>>(step, ostep);

    // Tensor-core attention: 4x64-key chunks per block, 2 blocks/SM
    attn_tc<<<dim3(16, 8, 8), 256, ATTN_SMEM>>>(mem_k, mem_v, step);
    combine_kernel<<<4096, 128>>>(step);

    // Output projection: RED epilogue into zeroed out region
    cudaMemsetAsync(out, 0, (size_t)524288 * 4, 0);
    gemm_tc<<<dim3(64, 16), 256, GEMM_SMEM>>>(ah, al, wo, so, wo, so, wo, so,
                                              out, 1, 256);

    // Join copy stream, then scatter the 16 new rows into kc/vc
    if (sok) cudaStreamWaitEvent(0, ev1, 0);
    scatter_new<<<512, 256>>>(step, kc, vc);
}